// round 5
// baseline (speedup 1.0000x reference)
#include <cuda_runtime.h>
#include <math.h>

#define BB 2
#define SS 2048
#define DM 768
#define NH 12
#define DH 64
#define MROWS (BB*SS)

static const long long OUT_ELEMS  = (long long)BB * SS * DM;            // 3,145,728
static const long long ATTN_ELEMS = (long long)BB * NH * SS * SS;       // 100,663,296

// Scratch (allocation-free rule: static __device__ arrays)
__device__ float g_Q[MROWS * DM];
__device__ float g_K[MROWS * DM];
__device__ float g_V[MROWS * DM];
__device__ float g_ctx[MROWS * DM];
__device__ float g_attn_scratch[(long long)BB * NH * SS * SS];

// ---------------------------------------------------------------------------
// Generic tiled SGEMM.
//   TRANS_B = true :  C[m,n] = alpha * sum_k A[m,k] * B[n,k]  (+ bias[n])
//   TRANS_B = false:  C[m,n] = alpha * sum_k A[m,k] * B[k,n]  (+ bias[n])
// Batched via blockIdx.z with (b, h) split offsets: z = zb*nh + zh.
// BM=BN=64, BK=16, 256 threads, 4x4 per thread.
// ---------------------------------------------------------------------------
template <bool TRANS_B>
__global__ void gemm_kernel(const float* __restrict__ A,
                            const float* __restrict__ Bm,
                            const float* __restrict__ bias,
                            float* __restrict__ C,
                            int M, int N, int K,
                            int lda, int ldb, int ldc,
                            float alpha, int nh,
                            long long sAb, long long sAh,
                            long long sBb, long long sBh,
                            long long sCb, long long sCh)
{
    __shared__ __align__(16) float As[16][68];   // k-major, padded
    __shared__ __align__(16) float Bs[16][68];

    const int tx = threadIdx.x;          // 0..15
    const int ty = threadIdx.y;          // 0..15
    const int tid = ty * 16 + tx;

    const int zb = blockIdx.z / nh;
    const int zh = blockIdx.z % nh;
    A  += zb * sAb + zh * sAh;
    Bm += zb * sBb + zh * sBh;
    C  += zb * sCb + zh * sCh;

    const int row0 = blockIdx.y * 64;
    const int col0 = blockIdx.x * 64;

    float acc[4][4];
#pragma unroll
    for (int i = 0; i < 4; ++i)
#pragma unroll
        for (int j = 0; j < 4; ++j) acc[i][j] = 0.0f;

    for (int k0 = 0; k0 < K; k0 += 16) {
        // Load A tile (64 rows x 16 k) -> As[k][m]
#pragma unroll
        for (int i = 0; i < 4; ++i) {
            int idx = tid + i * 256;
            int r = idx >> 4;
            int c = idx & 15;
            As[c][r] = A[(long long)(row0 + r) * lda + (k0 + c)];
        }
        if (TRANS_B) {
            // B is [N,K] row-major -> Bs[k][n]
#pragma unroll
            for (int i = 0; i < 4; ++i) {
                int idx = tid + i * 256;
                int r = idx >> 4;
                int c = idx & 15;
                Bs[c][r] = Bm[(long long)(col0 + r) * ldb + (k0 + c)];
            }
        } else {
            // B is [K,N] row-major -> Bs[k][n]
#pragma unroll
            for (int i = 0; i < 4; ++i) {
                int kk = (tid >> 6) + i * 4;
                int n  = tid & 63;
                Bs[kk][n] = Bm[(long long)(k0 + kk) * ldb + (col0 + n)];
            }
        }
        __syncthreads();

#pragma unroll
        for (int kk = 0; kk < 16; ++kk) {
            float4 a  = *(const float4*)&As[kk][ty * 4];
            float4 bb = *(const float4*)&Bs[kk][tx * 4];
            acc[0][0] += a.x * bb.x; acc[0][1] += a.x * bb.y;
            acc[0][2] += a.x * bb.z; acc[0][3] += a.x * bb.w;
            acc[1][0] += a.y * bb.x; acc[1][1] += a.y * bb.y;
            acc[1][2] += a.y * bb.z; acc[1][3] += a.y * bb.w;
            acc[2][0] += a.z * bb.x; acc[2][1] += a.z * bb.y;
            acc[2][2] += a.z * bb.z; acc[2][3] += a.z * bb.w;
            acc[3][0] += a.w * bb.x; acc[3][1] += a.w * bb.y;
            acc[3][2] += a.w * bb.z; acc[3][3] += a.w * bb.w;
        }
        __syncthreads();
    }

    float4 bv = make_float4(0.f, 0.f, 0.f, 0.f);
    if (bias) {
        bv.x = bias[col0 + tx * 4 + 0];
        bv.y = bias[col0 + tx * 4 + 1];
        bv.z = bias[col0 + tx * 4 + 2];
        bv.w = bias[col0 + tx * 4 + 3];
    }
#pragma unroll
    for (int i = 0; i < 4; ++i) {
        long long m = row0 + ty * 4 + i;
        float4 v;
        v.x = alpha * acc[i][0] + bv.x;
        v.y = alpha * acc[i][1] + bv.y;
        v.z = alpha * acc[i][2] + bv.z;
        v.w = alpha * acc[i][3] + bv.w;
        *(float4*)&C[m * ldc + col0 + tx * 4] = v;
    }
}

// ---------------------------------------------------------------------------
// In-place row softmax over rows of length SS. One block (256 thr) per row.
// ---------------------------------------------------------------------------
__global__ void softmax_rows(float* __restrict__ data)
{
    long long row = blockIdx.x;
    float* p = data + row * (long long)SS;
    __shared__ float red[256];
    const int t = threadIdx.x;

    float m = -1e30f;
    for (int i = t; i < SS; i += 256) m = fmaxf(m, p[i]);
    red[t] = m;
    __syncthreads();
    for (int s = 128; s > 0; s >>= 1) {
        if (t < s) red[t] = fmaxf(red[t], red[t + s]);
        __syncthreads();
    }
    m = red[0];
    __syncthreads();

    float sum = 0.0f;
    for (int i = t; i < SS; i += 256) {
        float e = expf(p[i] - m);
        p[i] = e;
        sum += e;
    }
    red[t] = sum;
    __syncthreads();
    for (int s = 128; s > 0; s >>= 1) {
        if (t < s) red[t] += red[t + s];
        __syncthreads();
    }
    float inv = 1.0f / red[0];
    __syncthreads();
    for (int i = t; i < SS; i += 256) p[i] *= inv;
}

// ---------------------------------------------------------------------------
extern "C" void kernel_launch(void* const* d_in, const int* in_sizes, int n_in,
                              void* d_out, int out_size)
{
    const float* query = (const float*)d_in[0];
    const float* key_  = (const float*)d_in[1];
    const float* value = (const float*)d_in[2];
    const float* W_q   = (const float*)d_in[3];
    const float* b_q   = (const float*)d_in[4];
    const float* W_k   = (const float*)d_in[5];
    const float* b_k   = (const float*)d_in[6];
    const float* W_v   = (const float*)d_in[7];
    const float* b_v   = (const float*)d_in[8];
    const float* W_o   = (const float*)d_in[9];
    const float* b_o   = (const float*)d_in[10];

    float* out = (float*)d_out;

    static float *pQ = nullptr, *pK = nullptr, *pV = nullptr, *pCtx = nullptr,
                 *pAttnScratch = nullptr;
    if (!pQ) {
        cudaGetSymbolAddress((void**)&pQ, g_Q);
        cudaGetSymbolAddress((void**)&pK, g_K);
        cudaGetSymbolAddress((void**)&pV, g_V);
        cudaGetSymbolAddress((void**)&pCtx, g_ctx);
        cudaGetSymbolAddress((void**)&pAttnScratch, g_attn_scratch);
    }

    // attn destination: second region of d_out if it fits, else scratch.
    float* attn = pAttnScratch;
    if ((long long)out_size >= OUT_ELEMS + ATTN_ELEMS)
        attn = out + OUT_ELEMS;

    dim3 blk(16, 16);

    // 1-3) Q/K/V projections: [4096,768] = X @ W^T + b
    {
        dim3 grd(DM / 64, MROWS / 64, 1);
        gemm_kernel<true><<<grd, blk>>>(query, W_q, b_q, pQ,
                                        MROWS, DM, DM, DM, DM, DM,
                                        1.0f, 1, 0, 0, 0, 0, 0, 0);
        gemm_kernel<true><<<grd, blk>>>(key_, W_k, b_k, pK,
                                        MROWS, DM, DM, DM, DM, DM,
                                        1.0f, 1, 0, 0, 0, 0, 0, 0);
        gemm_kernel<true><<<grd, blk>>>(value, W_v, b_v, pV,
                                        MROWS, DM, DM, DM, DM, DM,
                                        1.0f, 1, 0, 0, 0, 0, 0, 0);
    }

    // 4) scores[b,h,q,k] = (Q . K) / 8  -> attn region
    {
        dim3 grd(SS / 64, SS / 64, BB * NH);
        gemm_kernel<true><<<grd, blk>>>(pQ, pK, nullptr, attn,
                                        SS, SS, DH, DM, DM, SS,
                                        0.125f, NH,
                                        (long long)SS * DM, DH,
                                        (long long)SS * DM, DH,
                                        (long long)NH * SS * SS, (long long)SS * SS);
    }

    // 5) softmax in place
    softmax_rows<<<BB * NH * SS, 256>>>(attn);

    // 6) ctx[b,q,h*64+d] = attn @ V
    {
        dim3 grd(DH / 64, SS / 64, BB * NH);
        gemm_kernel<false><<<grd, blk>>>(attn, pV, nullptr, pCtx,
                                         SS, DH, SS, SS, DM, DM,
                                         1.0f, NH,
                                         (long long)NH * SS * SS, (long long)SS * SS,
                                         (long long)SS * DM, DH,
                                         (long long)SS * DM, DH);
    }

    // 7) out = ctx @ W_o^T + b_o
    {
        dim3 grd(DM / 64, MROWS / 64, 1);
        gemm_kernel<true><<<grd, blk>>>(pCtx, W_o, b_o, out,
                                        MROWS, DM, DM, DM, DM, DM,
                                        1.0f, 1, 0, 0, 0, 0, 0, 0);
    }
}

// round 8
// speedup vs baseline: 1.7384x; 1.7384x over previous
#include <cuda_runtime.h>
#include <cuda_bf16.h>
#include <math.h>
#include <stdint.h>

#define BB 2
#define SS 2048
#define DM 768
#define NH 12
#define DH 64
#define MROWS (BB*SS)

static const long long OUT_ELEMS  = (long long)BB * SS * DM;            // 3,145,728
static const long long ATTN_ELEMS = (long long)BB * NH * SS * SS;       // 100,663,296

// Scratch (allocation-free rule: static __device__ arrays)
__device__ float g_Q[MROWS * DM];
__device__ float g_K[MROWS * DM];
__device__ float g_V[MROWS * DM];
__device__ float g_ctx[MROWS * DM];
__device__ float g_attn_scratch[(long long)BB * NH * SS * SS];

// ---------------------------------------------------------------------------
// bf16 split helpers: x = hi + lo, both bf16, fp32-recoverable to ~2^-17.
// ---------------------------------------------------------------------------
__device__ __forceinline__ void split2(float x, float y, uint32_t& h, uint32_t& l)
{
    __nv_bfloat16 hx = __float2bfloat16_rn(x);
    __nv_bfloat16 hy = __float2bfloat16_rn(y);
    float lx = x - __bfloat162float(hx);
    float ly = y - __bfloat162float(hy);
    __nv_bfloat16 lbx = __float2bfloat16_rn(lx);
    __nv_bfloat16 lby = __float2bfloat16_rn(ly);
    h = (uint32_t)__bfloat16_as_ushort(hx) | ((uint32_t)__bfloat16_as_ushort(hy) << 16);
    l = (uint32_t)__bfloat16_as_ushort(lbx) | ((uint32_t)__bfloat16_as_ushort(lby) << 16);
}

__device__ __forceinline__ void split1(float x, unsigned short& h, unsigned short& l)
{
    __nv_bfloat16 hx = __float2bfloat16_rn(x);
    float lx = x - __bfloat162float(hx);
    h = __bfloat16_as_ushort(hx);
    l = __bfloat16_as_ushort(__float2bfloat16_rn(lx));
}

__device__ __forceinline__ void mma16816(float d[4], const uint32_t a[4], const uint32_t b[2])
{
    asm volatile(
        "mma.sync.aligned.m16n8k16.row.col.f32.bf16.bf16.f32 "
        "{%0,%1,%2,%3}, {%4,%5,%6,%7}, {%8,%9}, {%0,%1,%2,%3};"
        : "+f"(d[0]), "+f"(d[1]), "+f"(d[2]), "+f"(d[3])
        : "r"(a[0]), "r"(a[1]), "r"(a[2]), "r"(a[3]), "r"(b[0]), "r"(b[1]));
}

// ---------------------------------------------------------------------------
// Tensor-core GEMM with 3-term bf16 split (fp32-accurate to ~1e-5):
//   TRANS_B = true :  C[m,n] = alpha * sum_k A[m,k] * B[n,k]  (+ bias[n])
//   TRANS_B = false:  C[m,n] = alpha * sum_k A[m,k] * B[k,n]  (+ bias[n])
// BM=128, BK=32, BN template (128 or 64). 256 threads, 8 warps (WM x WN grid).
// Batched via blockIdx.z = zb*nh + zh with per-(b,h) pointer strides.
// Requires M%128==0, N%BN==0, K%32==0 (true for all shapes here).
// ---------------------------------------------------------------------------
template <int BN, bool TRANS_B, int WM>
__global__ __launch_bounds__(256) void gemm_bf16x3(
    const float* __restrict__ A, const float* __restrict__ Bm,
    const float* __restrict__ bias, float* __restrict__ C,
    int K, int lda, int ldb, int ldc, float alpha, int nh,
    long long sAb, long long sAh, long long sBb, long long sBh,
    long long sCb, long long sCh)
{
    constexpr int BM = 128, BK = 32;
    constexpr int WN  = 8 / WM;
    constexpr int WTM = BM / WM;          // rows per warp (64 or 32)
    constexpr int WTN = BN / WN;          // cols per warp (32)
    constexpr int TM  = WTM / 16;         // m16 tiles per warp (4 or 2)
    constexpr int TN  = WTN / 8;          // n8 tiles per warp (4)
    constexpr int KU  = BK / 2 + 1;       // u32 per row (16 + 1 pad)

    __shared__ uint32_t Ah[BM][KU], Al[BM][KU];
    __shared__ uint32_t Bh[BN][KU], Bl[BN][KU];

    const int tid  = threadIdx.x;
    const int lane = tid & 31;
    const int warp = tid >> 5;
    const int g = lane >> 2;              // group row (0..7)
    const int t = lane & 3;               // quad id  (0..3)
    const int wm = warp % WM, wn = warp / WM;
    const int wrow0 = wm * WTM, wcol0 = wn * WTN;

    const int zb = blockIdx.z / nh, zh = blockIdx.z % nh;
    A  += zb * sAb + zh * sAh;
    Bm += zb * sBb + zh * sBh;
    C  += zb * sCb + zh * sCh;

    const int row0 = blockIdx.y * BM;
    const int col0 = blockIdx.x * BN;

    float acc[TM][TN][4] = {};

    constexpr int AF4 = (BM * BK) / 1024;   // float4 loads of A per thread (4)
    constexpr int BF4 = (BN * BK) / 1024;   // float4 loads of B per thread (4 or 2)
    float4 ra[AF4], rb[BF4];

    const int KT = K / BK;

    // ---- gmem -> regs ----
    auto loadA = [&](int k0) {
#pragma unroll
        for (int i = 0; i < AF4; ++i) {
            int r = tid / 8 + i * 32;
            int c = (tid & 7) * 4;
            ra[i] = *(const float4*)&A[(long long)(row0 + r) * lda + k0 + c];
        }
    };
    auto loadB = [&](int k0) {
        if (TRANS_B) {
#pragma unroll
            for (int i = 0; i < BF4; ++i) {
                int r = tid / 8 + i * 32;       // n-row within tile
                int c = (tid & 7) * 4;
                rb[i] = *(const float4*)&Bm[(long long)(col0 + r) * ldb + k0 + c];
            }
        } else {
            constexpr int F4PR = BN / 4;        // float4 per k-row
            constexpr int RP   = 256 / F4PR;    // k-rows per pass
#pragma unroll
            for (int i = 0; i < BF4; ++i) {
                int k = tid / F4PR + i * RP;
                int c = (tid % F4PR) * 4;
                rb[i] = *(const float4*)&Bm[(long long)(k0 + k) * ldb + col0 + c];
            }
        }
    };

    // ---- regs -> smem (with bf16 hi/lo split) ----
    auto storeA = [&]() {
#pragma unroll
        for (int i = 0; i < AF4; ++i) {
            int r  = tid / 8 + i * 32;
            int cu = (tid & 7) * 2;
            uint32_t h0, l0, h1, l1;
            split2(ra[i].x, ra[i].y, h0, l0);
            split2(ra[i].z, ra[i].w, h1, l1);
            Ah[r][cu] = h0; Ah[r][cu + 1] = h1;
            Al[r][cu] = l0; Al[r][cu + 1] = l1;
        }
    };
    auto storeB = [&]() {
        if (TRANS_B) {
#pragma unroll
            for (int i = 0; i < BF4; ++i) {
                int r  = tid / 8 + i * 32;
                int cu = (tid & 7) * 2;
                uint32_t h0, l0, h1, l1;
                split2(rb[i].x, rb[i].y, h0, l0);
                split2(rb[i].z, rb[i].w, h1, l1);
                Bh[r][cu] = h0; Bh[r][cu + 1] = h1;
                Bl[r][cu] = l0; Bl[r][cu + 1] = l1;
            }
        } else {
            constexpr int F4PR = BN / 4;
            constexpr int RP   = 256 / F4PR;
#pragma unroll
            for (int i = 0; i < BF4; ++i) {
                int k  = tid / F4PR + i * RP;
                int n0 = (tid % F4PR) * 4;
                float v[4] = { rb[i].x, rb[i].y, rb[i].z, rb[i].w };
#pragma unroll
                for (int j = 0; j < 4; ++j) {
                    unsigned short hs, ls;
                    split1(v[j], hs, ls);
                    ((unsigned short*)&Bh[n0 + j][0])[k] = hs;
                    ((unsigned short*)&Bl[n0 + j][0])[k] = ls;
                }
            }
        }
    };

    // ---- compute one BK=32 slab from smem ----
    auto compute = [&]() {
#pragma unroll
        for (int ks = 0; ks < 2; ++ks) {
            uint32_t bh[TN][2], bl[TN][2];
#pragma unroll
            for (int nt = 0; nt < TN; ++nt) {
                int n = wcol0 + nt * 8 + g;
                int c = t + ks * 8;
                bh[nt][0] = Bh[n][c]; bh[nt][1] = Bh[n][c + 4];
                bl[nt][0] = Bl[n][c]; bl[nt][1] = Bl[n][c + 4];
            }
#pragma unroll
            for (int mt = 0; mt < TM; ++mt) {
                int m = wrow0 + mt * 16 + g;
                int c = t + ks * 8;
                uint32_t ah[4] = { Ah[m][c], Ah[m + 8][c], Ah[m][c + 4], Ah[m + 8][c + 4] };
                uint32_t al[4] = { Al[m][c], Al[m + 8][c], Al[m][c + 4], Al[m + 8][c + 4] };
#pragma unroll
                for (int nt = 0; nt < TN; ++nt) {
                    mma16816(acc[mt][nt], ah, bh[nt]);   // hi*hi
                    mma16816(acc[mt][nt], ah, bl[nt]);   // hi*lo
                    mma16816(acc[mt][nt], al, bh[nt]);   // lo*hi
                }
            }
        }
    };

    // ---- pipelined mainloop ----
    loadA(0); loadB(0);
    storeA(); storeB();
    __syncthreads();
    for (int kt = 0; kt < KT; ++kt) {
        if (kt + 1 < KT) { loadA((kt + 1) * BK); loadB((kt + 1) * BK); }
        compute();
        __syncthreads();
        if (kt + 1 < KT) { storeA(); storeB(); __syncthreads(); }
    }

    // ---- epilogue ----
#pragma unroll
    for (int mt = 0; mt < TM; ++mt) {
#pragma unroll
        for (int nt = 0; nt < TN; ++nt) {
            int m = row0 + wrow0 + mt * 16 + g;
            int n = col0 + wcol0 + nt * 8 + 2 * t;
            float b0 = 0.f, b1 = 0.f;
            if (bias) { b0 = bias[n]; b1 = bias[n + 1]; }
            float2 v0, v1;
            v0.x = alpha * acc[mt][nt][0] + b0;
            v0.y = alpha * acc[mt][nt][1] + b1;
            v1.x = alpha * acc[mt][nt][2] + b0;
            v1.y = alpha * acc[mt][nt][3] + b1;
            *(float2*)&C[(long long)m * ldc + n] = v0;
            *(float2*)&C[(long long)(m + 8) * ldc + n] = v1;
        }
    }
}

// ---------------------------------------------------------------------------
// In-place row softmax over rows of length SS. One block (256 thr) per row.
// ---------------------------------------------------------------------------
__global__ void softmax_rows(float* __restrict__ data)
{
    long long row = blockIdx.x;
    float* p = data + row * (long long)SS;
    __shared__ float red[256];
    const int t = threadIdx.x;

    float4* p4 = (float4*)p;
    const int n4 = SS / 4;   // 512

    float m = -1e30f;
    for (int i = t; i < n4; i += 256) {
        float4 v = p4[i];
        m = fmaxf(m, fmaxf(fmaxf(v.x, v.y), fmaxf(v.z, v.w)));
    }
    red[t] = m;
    __syncthreads();
    for (int s = 128; s > 0; s >>= 1) {
        if (t < s) red[t] = fmaxf(red[t], red[t + s]);
        __syncthreads();
    }
    m = red[0];
    __syncthreads();

    float sum = 0.0f;
    for (int i = t; i < n4; i += 256) {
        float4 v = p4[i];
        v.x = expf(v.x - m); v.y = expf(v.y - m);
        v.z = expf(v.z - m); v.w = expf(v.w - m);
        p4[i] = v;
        sum += v.x + v.y + v.z + v.w;
    }
    red[t] = sum;
    __syncthreads();
    for (int s = 128; s > 0; s >>= 1) {
        if (t < s) red[t] += red[t + s];
        __syncthreads();
    }
    float inv = 1.0f / red[0];
    __syncthreads();
    for (int i = t; i < n4; i += 256) {
        float4 v = p4[i];
        v.x *= inv; v.y *= inv; v.z *= inv; v.w *= inv;
        p4[i] = v;
    }
}

// ---------------------------------------------------------------------------
extern "C" void kernel_launch(void* const* d_in, const int* in_sizes, int n_in,
                              void* d_out, int out_size)
{
    const float* query = (const float*)d_in[0];
    const float* key_  = (const float*)d_in[1];
    const float* value = (const float*)d_in[2];
    const float* W_q   = (const float*)d_in[3];
    const float* b_q   = (const float*)d_in[4];
    const float* W_k   = (const float*)d_in[5];
    const float* b_k   = (const float*)d_in[6];
    const float* W_v   = (const float*)d_in[7];
    const float* b_v   = (const float*)d_in[8];
    const float* W_o   = (const float*)d_in[9];
    const float* b_o   = (const float*)d_in[10];

    float* out = (float*)d_out;

    static float *pQ = nullptr, *pK = nullptr, *pV = nullptr, *pCtx = nullptr,
                 *pAttnScratch = nullptr;
    if (!pQ) {
        cudaGetSymbolAddress((void**)&pQ, g_Q);
        cudaGetSymbolAddress((void**)&pK, g_K);
        cudaGetSymbolAddress((void**)&pV, g_V);
        cudaGetSymbolAddress((void**)&pCtx, g_ctx);
        cudaGetSymbolAddress((void**)&pAttnScratch, g_attn_scratch);
    }

    // attn destination: second region of d_out if it fits, else scratch.
    float* attn = pAttnScratch;
    if ((long long)out_size >= OUT_ELEMS + ATTN_ELEMS)
        attn = out + OUT_ELEMS;

    // 1-3) Q/K/V projections: [4096,768] = X @ W^T + b
    {
        dim3 grd(DM / 128, MROWS / 128, 1);
        gemm_bf16x3<128, true, 2><<<grd, 256>>>(query, W_q, b_q, pQ,
                                                DM, DM, DM, DM, 1.0f, 1,
                                                0, 0, 0, 0, 0, 0);
        gemm_bf16x3<128, true, 2><<<grd, 256>>>(key_, W_k, b_k, pK,
                                                DM, DM, DM, DM, 1.0f, 1,
                                                0, 0, 0, 0, 0, 0);
        gemm_bf16x3<128, true, 2><<<grd, 256>>>(value, W_v, b_v, pV,
                                                DM, DM, DM, DM, 1.0f, 1,
                                                0, 0, 0, 0, 0, 0);
    }

    // 4) scores[b,h,q,k] = (Q . K) / 8  -> attn region
    {
        dim3 grd(SS / 128, SS / 128, BB * NH);
        gemm_bf16x3<128, true, 2><<<grd, 256>>>(pQ, pK, nullptr, attn,
                                                DH, DM, DM, SS, 0.125f, NH,
                                                (long long)SS * DM, DH,
                                                (long long)SS * DM, DH,
                                                (long long)NH * SS * SS,
                                                (long long)SS * SS);
    }

    // 5) softmax in place
    softmax_rows<<<BB * NH * SS, 256>>>(attn);

    // 6) ctx[b,q,h*64+d] = attn @ V
    {
        dim3 grd(DH / 64, SS / 128, BB * NH);
        gemm_bf16x3<64, false, 4><<<grd, 256>>>(attn, pV, nullptr, pCtx,
                                                SS, SS, DM, DM, 1.0f, NH,
                                                (long long)NH * SS * SS,
                                                (long long)SS * SS,
                                                (long long)SS * DM, DH,
                                                (long long)SS * DM, DH);
    }

    // 7) out = ctx @ W_o^T + b_o
    {
        dim3 grd(DM / 128, MROWS / 128, 1);
        gemm_bf16x3<128, true, 2><<<grd, 256>>>(pCtx, W_o, b_o, out,
                                                DM, DM, DM, DM, 1.0f, 1,
                                                0, 0, 0, 0, 0, 0);
    }
}

// round 12
// speedup vs baseline: 2.0265x; 1.1657x over previous
#include <cuda_runtime.h>
#include <cuda_bf16.h>
#include <math.h>
#include <stdint.h>

#define BB 2
#define SS 2048
#define DM 768
#define NH 12
#define DH 64
#define MROWS (BB*SS)

static const long long OUT_ELEMS  = (long long)BB * SS * DM;            // 3,145,728
static const long long ATTN_ELEMS = (long long)BB * NH * SS * SS;       // 100,663,296

// ---------------------------------------------------------------------------
// Scratch (allocation-free rule: static __device__ arrays), all bf16 hi/lo
// pairs stored as unsigned short. 16B-aligned for cp.async.
// ---------------------------------------------------------------------------
__device__ __align__(16) unsigned short g_xqh[MROWS*DM], g_xql[MROWS*DM];
__device__ __align__(16) unsigned short g_xkh[MROWS*DM], g_xkl[MROWS*DM];
__device__ __align__(16) unsigned short g_xvh[MROWS*DM], g_xvl[MROWS*DM];
__device__ __align__(16) unsigned short g_wqh[DM*DM], g_wql[DM*DM];
__device__ __align__(16) unsigned short g_wkh[DM*DM], g_wkl[DM*DM];
__device__ __align__(16) unsigned short g_wvh[DM*DM], g_wvl[DM*DM];
__device__ __align__(16) unsigned short g_woh[DM*DM], g_wol[DM*DM];
__device__ __align__(16) unsigned short g_Qh[MROWS*DM], g_Ql[MROWS*DM];
__device__ __align__(16) unsigned short g_Kh[MROWS*DM], g_Kl[MROWS*DM];
__device__ __align__(16) unsigned short g_VTh[BB*NH*DH*SS], g_VTl[BB*NH*DH*SS]; // [(b,h,d)][s]
__device__ __align__(16) unsigned short g_ch[MROWS*DM], g_cl[MROWS*DM];
__device__ __align__(16) unsigned short g_ah[BB*NH*SS*SS], g_al[BB*NH*SS*SS];
__device__ __align__(16) float g_attn_f[(long long)BB*NH*SS*SS];   // fallback if attn not in d_out

// ---------------------------------------------------------------------------
// helpers
// ---------------------------------------------------------------------------
__device__ __forceinline__ void cp16(uint32_t saddr, const void* gptr)
{
    asm volatile("cp.async.cg.shared.global [%0], [%1], 16;" :: "r"(saddr), "l"(gptr));
}

__device__ __forceinline__ void mma16816(float d[4], const uint32_t a[4], const uint32_t b[2])
{
    asm volatile(
        "mma.sync.aligned.m16n8k16.row.col.f32.bf16.bf16.f32 "
        "{%0,%1,%2,%3}, {%4,%5,%6,%7}, {%8,%9}, {%0,%1,%2,%3};"
        : "+f"(d[0]), "+f"(d[1]), "+f"(d[2]), "+f"(d[3])
        : "r"(a[0]), "r"(a[1]), "r"(a[2]), "r"(a[3]), "r"(b[0]), "r"(b[1]));
}

__device__ __forceinline__ unsigned short us(__nv_bfloat16 h) { return __bfloat16_as_ushort(h); }

__device__ __forceinline__ void store_split2(unsigned short* ph, unsigned short* pl,
                                             float x, float y)
{
    __nv_bfloat16 hx = __float2bfloat16_rn(x), hy = __float2bfloat16_rn(y);
    __nv_bfloat16 lx = __float2bfloat16_rn(x - __bfloat162float(hx));
    __nv_bfloat16 ly = __float2bfloat16_rn(y - __bfloat162float(hy));
    ushort2 hv; hv.x = us(hx); hv.y = us(hy);
    ushort2 lv; lv.x = us(lx); lv.y = us(ly);
    *(ushort2*)ph = hv; *(ushort2*)pl = lv;
}

__device__ __forceinline__ void store_split1(unsigned short* ph, unsigned short* pl, float x)
{
    __nv_bfloat16 hx = __float2bfloat16_rn(x);
    __nv_bfloat16 lx = __float2bfloat16_rn(x - __bfloat162float(hx));
    *ph = us(hx); *pl = us(lx);
}

__device__ __forceinline__ void pack4(float4 v, uint2& h, uint2& l)
{
    __nv_bfloat16 h0 = __float2bfloat16_rn(v.x), h1 = __float2bfloat16_rn(v.y);
    __nv_bfloat16 h2 = __float2bfloat16_rn(v.z), h3 = __float2bfloat16_rn(v.w);
    __nv_bfloat16 l0 = __float2bfloat16_rn(v.x - __bfloat162float(h0));
    __nv_bfloat16 l1 = __float2bfloat16_rn(v.y - __bfloat162float(h1));
    __nv_bfloat16 l2 = __float2bfloat16_rn(v.z - __bfloat162float(h2));
    __nv_bfloat16 l3 = __float2bfloat16_rn(v.w - __bfloat162float(h3));
    h.x = (uint32_t)us(h0) | ((uint32_t)us(h1) << 16);
    h.y = (uint32_t)us(h2) | ((uint32_t)us(h3) << 16);
    l.x = (uint32_t)us(l0) | ((uint32_t)us(l1) << 16);
    l.y = (uint32_t)us(l2) | ((uint32_t)us(l3) << 16);
}

// ---------------------------------------------------------------------------
// split fp32 array -> bf16 hi/lo arrays
// ---------------------------------------------------------------------------
__global__ void split_arr(const float4* __restrict__ x, uint2* __restrict__ h,
                          uint2* __restrict__ l, int n4)
{
    int i = blockIdx.x * blockDim.x + threadIdx.x;
    if (i >= n4) return;
    uint2 hp, lp;
    pack4(x[i], hp, lp);
    h[i] = hp; l[i] = lp;
}

// ---------------------------------------------------------------------------
// Pre-split bf16 tensor-core GEMM (3-term):  C[m,n] = alpha*sum_k A[m,k]*B[n,k] + bias[n]
// A,B given as hi/lo bf16 arrays (row-major, B stored [n][k]).
// BM=128, BK=32, 256 threads, cp.async double-buffered.
// EPI: 0 = fp32 C, 1 = split hi/lo C, 2 = split hi/lo transposed (V^T layout).
// ---------------------------------------------------------------------------
template <int BN, int EPI>
__global__ __launch_bounds__(256, 2) void gemm_sp(
    const unsigned short* __restrict__ Ahg, const unsigned short* __restrict__ Alg,
    const unsigned short* __restrict__ Bhg, const unsigned short* __restrict__ Blg,
    const float* __restrict__ bias,
    float* __restrict__ Cf, unsigned short* __restrict__ Ch, unsigned short* __restrict__ Cl,
    int K, int lda, int ldb, int ldc, float alpha, int nh,
    long long sAb, long long sAh, long long sBb, long long sBh,
    long long sCb, long long sCh)
{
    constexpr int BM = 128;
    constexpr int WM = (BN == 128) ? 2 : 4;
    constexpr int WN = 8 / WM;
    constexpr int WTM = BM / WM;
    constexpr int WTN = BN / WN;
    constexpr int TM = WTM / 16;
    constexpr int TN = WTN / 8;
    constexpr int ROWU = 20;                 // u32 per smem row: 16 data + 4 pad (80B stride)
    constexpr int ASZ = BM * ROWU;
    constexpr int BSZ = BN * ROWU;

    extern __shared__ uint32_t sm[];
    uint32_t* sAh_ = sm;                     // [2][ASZ]
    uint32_t* sAl_ = sm + 2 * ASZ;
    uint32_t* sBh_ = sm + 4 * ASZ;
    uint32_t* sBl_ = sBh_ + 2 * BSZ;

    const int tid = threadIdx.x, lane = tid & 31, warp = tid >> 5;
    const int g = lane >> 2, t = lane & 3;
    const int wm = warp % WM, wn = warp / WM;
    const int wrow0 = wm * WTM, wcol0 = wn * WTN;

    const int zb = blockIdx.z / nh, zh = blockIdx.z % nh;
    const long long aoff = zb * sAb + zh * sAh;
    const long long boff = zb * sBb + zh * sBh;
    const long long coff = zb * sCb + zh * sCh;
    Ahg += aoff; Alg += aoff; Bhg += boff; Blg += boff;

    const int row0 = blockIdx.y * BM;
    const int col0 = blockIdx.x * BN;

    const uint32_t aAh = (uint32_t)__cvta_generic_to_shared(sAh_);
    const uint32_t aAl = (uint32_t)__cvta_generic_to_shared(sAl_);
    const uint32_t aBh = (uint32_t)__cvta_generic_to_shared(sBh_);
    const uint32_t aBl = (uint32_t)__cvta_generic_to_shared(sBl_);

    float acc[TM][TN][4] = {};
    const int KT = K / 32;

    // A slab row = 32 bf16 = 64B = FOUR 16B chunks. 2 threads/row, each thread
    // copies TWO chunks per array (this was the R11 bug: only one chunk each).
    auto load_slab = [&](int kt, int buf) {
        const int k0 = kt * 32;
        {
            int r = tid >> 1, c = tid & 1;                 // c: low/high 16 ushorts
            long long go = (long long)(row0 + r) * lda + k0 + c * 16;
            uint32_t so = (uint32_t)(buf * ASZ + r * ROWU + c * 8) * 4u;
            cp16(aAh + so,      Ahg + go);
            cp16(aAh + so + 16, Ahg + go + 8);
            cp16(aAl + so,      Alg + go);
            cp16(aAl + so + 16, Alg + go + 8);
        }
        if (BN == 128) {
            int r = tid >> 1, c = tid & 1;
            long long go = (long long)(col0 + r) * ldb + k0 + c * 16;
            uint32_t so = (uint32_t)(buf * BSZ + r * ROWU + c * 8) * 4u;
            cp16(aBh + so,      Bhg + go);
            cp16(aBh + so + 16, Bhg + go + 8);
            cp16(aBl + so,      Blg + go);
            cp16(aBl + so + 16, Blg + go + 8);
        } else {
            int r = (tid & 127) >> 1, c = tid & 1;
            long long go = (long long)(col0 + r) * ldb + k0 + c * 16;
            uint32_t so = (uint32_t)(buf * BSZ + r * ROWU + c * 8) * 4u;
            if (tid < 128) {
                cp16(aBh + so,      Bhg + go);
                cp16(aBh + so + 16, Bhg + go + 8);
            } else {
                cp16(aBl + so,      Blg + go);
                cp16(aBl + so + 16, Blg + go + 8);
            }
        }
        asm volatile("cp.async.commit_group;" ::: "memory");
    };

    auto compute = [&](int buf) {
        const uint32_t* Abh = sAh_ + buf * ASZ;
        const uint32_t* Abl = sAl_ + buf * ASZ;
        const uint32_t* Bbh = sBh_ + buf * BSZ;
        const uint32_t* Bbl = sBl_ + buf * BSZ;
#pragma unroll
        for (int ks = 0; ks < 2; ++ks) {
            const int c = t + ks * 8;
            uint32_t bh[TN][2], bl[TN][2];
#pragma unroll
            for (int nt = 0; nt < TN; ++nt) {
                int n = wcol0 + nt * 8 + g;
                bh[nt][0] = Bbh[n * ROWU + c]; bh[nt][1] = Bbh[n * ROWU + c + 4];
                bl[nt][0] = Bbl[n * ROWU + c]; bl[nt][1] = Bbl[n * ROWU + c + 4];
            }
#pragma unroll
            for (int mt = 0; mt < TM; ++mt) {
                int m = wrow0 + mt * 16 + g;
                uint32_t ah[4] = { Abh[m*ROWU+c], Abh[(m+8)*ROWU+c],
                                   Abh[m*ROWU+c+4], Abh[(m+8)*ROWU+c+4] };
                uint32_t al[4] = { Abl[m*ROWU+c], Abl[(m+8)*ROWU+c],
                                   Abl[m*ROWU+c+4], Abl[(m+8)*ROWU+c+4] };
#pragma unroll
                for (int nt = 0; nt < TN; ++nt) {
                    mma16816(acc[mt][nt], ah, bh[nt]);   // hi*hi
                    mma16816(acc[mt][nt], ah, bl[nt]);   // hi*lo
                    mma16816(acc[mt][nt], al, bh[nt]);   // lo*hi
                }
            }
        }
    };

    load_slab(0, 0);
    for (int kt = 0; kt < KT; ++kt) {
        if (kt + 1 < KT) {
            load_slab(kt + 1, (kt + 1) & 1);
            asm volatile("cp.async.wait_group 1;" ::: "memory");
        } else {
            asm volatile("cp.async.wait_group 0;" ::: "memory");
        }
        __syncthreads();
        compute(kt & 1);
        __syncthreads();
    }

    // epilogue
#pragma unroll
    for (int mt = 0; mt < TM; ++mt) {
#pragma unroll
        for (int nt = 0; nt < TN; ++nt) {
            int m = row0 + wrow0 + mt * 16 + g;
            int n = col0 + wcol0 + nt * 8 + 2 * t;
            float b0 = 0.f, b1 = 0.f;
            if (bias) { b0 = bias[n]; b1 = bias[n + 1]; }
            float v00 = alpha * acc[mt][nt][0] + b0;
            float v01 = alpha * acc[mt][nt][1] + b1;
            float v10 = alpha * acc[mt][nt][2] + b0;
            float v11 = alpha * acc[mt][nt][3] + b1;
            if (EPI == 0) {
                float2 u0; u0.x = v00; u0.y = v01;
                float2 u1; u1.x = v10; u1.y = v11;
                *(float2*)&Cf[coff + (long long)m * ldc + n] = u0;
                *(float2*)&Cf[coff + (long long)(m + 8) * ldc + n] = u1;
            } else if (EPI == 1) {
                store_split2(Ch + coff + (long long)m * ldc + n,
                             Cl + coff + (long long)m * ldc + n, v00, v01);
                store_split2(Ch + coff + (long long)(m + 8) * ldc + n,
                             Cl + coff + (long long)(m + 8) * ldc + n, v10, v11);
            } else {
                // V^T layout: idx = ((b*NH + h)*64 + d)*SS + s, m=(b,s), n=(h,d)
                auto vt = [](int mm, int nn) -> long long {
                    int b = mm >> 11, s = mm & 2047, h = nn >> 6, d = nn & 63;
                    return (((long long)(b * NH + h) * DH + d) << 11) + s;
                };
                store_split1(Ch + vt(m, n),         Cl + vt(m, n),         v00);
                store_split1(Ch + vt(m, n + 1),     Cl + vt(m, n + 1),     v01);
                store_split1(Ch + vt(m + 8, n),     Cl + vt(m + 8, n),     v10);
                store_split1(Ch + vt(m + 8, n + 1), Cl + vt(m + 8, n + 1), v11);
            }
        }
    }
}

// ---------------------------------------------------------------------------
// Single-pass softmax: row (2048 fp32) in registers, one read + one write of
// fp32 attn + bf16 hi/lo split for the AV GEMM.
// ---------------------------------------------------------------------------
__global__ __launch_bounds__(256) void softmax_fused(float* __restrict__ attn,
                                                     unsigned short* __restrict__ ah,
                                                     unsigned short* __restrict__ al)
{
    const long long row = blockIdx.x;
    float4* p4 = (float4*)(attn + (row << 11));
    uint2*  ph = (uint2*)(ah + (row << 11));
    uint2*  pl = (uint2*)(al + (row << 11));
    const int t = threadIdx.x;
    __shared__ float red[256];

    float4 v[2];
    v[0] = p4[t];
    v[1] = p4[t + 256];

    float m = fmaxf(fmaxf(fmaxf(v[0].x, v[0].y), fmaxf(v[0].z, v[0].w)),
                    fmaxf(fmaxf(v[1].x, v[1].y), fmaxf(v[1].z, v[1].w)));
    red[t] = m; __syncthreads();
    for (int s = 128; s > 0; s >>= 1) {
        if (t < s) red[t] = fmaxf(red[t], red[t + s]);
        __syncthreads();
    }
    m = red[0]; __syncthreads();

    float sum = 0.f;
#pragma unroll
    for (int i = 0; i < 2; ++i) {
        v[i].x = __expf(v[i].x - m); v[i].y = __expf(v[i].y - m);
        v[i].z = __expf(v[i].z - m); v[i].w = __expf(v[i].w - m);
        sum += v[i].x + v[i].y + v[i].z + v[i].w;
    }
    red[t] = sum; __syncthreads();
    for (int s = 128; s > 0; s >>= 1) {
        if (t < s) red[t] += red[t + s];
        __syncthreads();
    }
    const float inv = 1.f / red[0];

#pragma unroll
    for (int i = 0; i < 2; ++i) {
        v[i].x *= inv; v[i].y *= inv; v[i].z *= inv; v[i].w *= inv;
        p4[t + i * 256] = v[i];
        uint2 hp, lp;
        pack4(v[i], hp, lp);
        ph[t + i * 256] = hp;
        pl[t + i * 256] = lp;
    }
}

// ---------------------------------------------------------------------------
extern "C" void kernel_launch(void* const* d_in, const int* in_sizes, int n_in,
                              void* d_out, int out_size)
{
    const float* query = (const float*)d_in[0];
    const float* key_  = (const float*)d_in[1];
    const float* value = (const float*)d_in[2];
    const float* W_q   = (const float*)d_in[3];
    const float* b_q   = (const float*)d_in[4];
    const float* W_k   = (const float*)d_in[5];
    const float* b_k   = (const float*)d_in[6];
    const float* W_v   = (const float*)d_in[7];
    const float* b_v   = (const float*)d_in[8];
    const float* W_o   = (const float*)d_in[9];
    const float* b_o   = (const float*)d_in[10];

    float* out = (float*)d_out;

    static bool inited = false;
    static unsigned short *xqh,*xql,*xkh,*xkl,*xvh,*xvl;
    static unsigned short *wqh,*wql,*wkh,*wkl,*wvh,*wvl,*woh,*wol;
    static unsigned short *Qh,*Ql,*Kh,*Kl,*VTh,*VTl,*ch,*cl,*ath,*atl;
    static float *attn_f;
    if (!inited) {
        inited = true;
        cudaGetSymbolAddress((void**)&xqh, g_xqh); cudaGetSymbolAddress((void**)&xql, g_xql);
        cudaGetSymbolAddress((void**)&xkh, g_xkh); cudaGetSymbolAddress((void**)&xkl, g_xkl);
        cudaGetSymbolAddress((void**)&xvh, g_xvh); cudaGetSymbolAddress((void**)&xvl, g_xvl);
        cudaGetSymbolAddress((void**)&wqh, g_wqh); cudaGetSymbolAddress((void**)&wql, g_wql);
        cudaGetSymbolAddress((void**)&wkh, g_wkh); cudaGetSymbolAddress((void**)&wkl, g_wkl);
        cudaGetSymbolAddress((void**)&wvh, g_wvh); cudaGetSymbolAddress((void**)&wvl, g_wvl);
        cudaGetSymbolAddress((void**)&woh, g_woh); cudaGetSymbolAddress((void**)&wol, g_wol);
        cudaGetSymbolAddress((void**)&Qh,  g_Qh);  cudaGetSymbolAddress((void**)&Ql,  g_Ql);
        cudaGetSymbolAddress((void**)&Kh,  g_Kh);  cudaGetSymbolAddress((void**)&Kl,  g_Kl);
        cudaGetSymbolAddress((void**)&VTh, g_VTh); cudaGetSymbolAddress((void**)&VTl, g_VTl);
        cudaGetSymbolAddress((void**)&ch,  g_ch);  cudaGetSymbolAddress((void**)&cl,  g_cl);
        cudaGetSymbolAddress((void**)&ath, g_ah);  cudaGetSymbolAddress((void**)&atl, g_al);
        cudaGetSymbolAddress((void**)&attn_f, g_attn_f);
        cudaFuncSetAttribute(gemm_sp<128,0>, cudaFuncAttributeMaxDynamicSharedMemorySize, 81920);
        cudaFuncSetAttribute(gemm_sp<128,1>, cudaFuncAttributeMaxDynamicSharedMemorySize, 81920);
        cudaFuncSetAttribute(gemm_sp<128,2>, cudaFuncAttributeMaxDynamicSharedMemorySize, 81920);
        cudaFuncSetAttribute(gemm_sp<64,1>,  cudaFuncAttributeMaxDynamicSharedMemorySize, 61440);
    }

    float* attn = attn_f;
    if ((long long)out_size >= OUT_ELEMS + ATTN_ELEMS)
        attn = out + OUT_ELEMS;

    // 0) split raw inputs + weights to bf16 hi/lo
    {
        int n4i = MROWS * DM / 4;     // 786432
        int n4w = DM * DM / 4;        // 147456
        split_arr<<<(n4i + 255) / 256, 256>>>((const float4*)query, (uint2*)xqh, (uint2*)xql, n4i);
        split_arr<<<(n4i + 255) / 256, 256>>>((const float4*)key_,  (uint2*)xkh, (uint2*)xkl, n4i);
        split_arr<<<(n4i + 255) / 256, 256>>>((const float4*)value, (uint2*)xvh, (uint2*)xvl, n4i);
        split_arr<<<(n4w + 255) / 256, 256>>>((const float4*)W_q, (uint2*)wqh, (uint2*)wql, n4w);
        split_arr<<<(n4w + 255) / 256, 256>>>((const float4*)W_k, (uint2*)wkh, (uint2*)wkl, n4w);
        split_arr<<<(n4w + 255) / 256, 256>>>((const float4*)W_v, (uint2*)wvh, (uint2*)wvl, n4w);
        split_arr<<<(n4w + 255) / 256, 256>>>((const float4*)W_o, (uint2*)woh, (uint2*)wol, n4w);
    }

    // 1-3) projections: Q,K split row-major; V split transposed (V^T per head)
    {
        dim3 grd(DM / 128, MROWS / 128, 1);
        gemm_sp<128,1><<<grd, 256, 81920>>>(xqh, xql, wqh, wql, b_q,
                                            nullptr, Qh, Ql,
                                            DM, DM, DM, DM, 1.0f, 1,
                                            0,0,0,0,0,0);
        gemm_sp<128,1><<<grd, 256, 81920>>>(xkh, xkl, wkh, wkl, b_k,
                                            nullptr, Kh, Kl,
                                            DM, DM, DM, DM, 1.0f, 1,
                                            0,0,0,0,0,0);
        gemm_sp<128,2><<<grd, 256, 81920>>>(xvh, xvl, wvh, wvl, b_v,
                                            nullptr, VTh, VTl,
                                            DM, DM, DM, 0, 1.0f, 1,
                                            0,0,0,0,0,0);
    }

    // 4) scores = (Q.K)/8 -> attn (fp32)
    {
        dim3 grd(SS / 128, SS / 128, BB * NH);
        gemm_sp<128,0><<<grd, 256, 81920>>>(Qh, Ql, Kh, Kl, nullptr,
                                            attn, nullptr, nullptr,
                                            DH, DM, DM, SS, 0.125f, NH,
                                            (long long)SS * DM, DH,
                                            (long long)SS * DM, DH,
                                            (long long)NH * SS * SS, (long long)SS * SS);
    }

    // 5) single-pass softmax: fp32 in-place + hi/lo split out
    softmax_fused<<<BB * NH * SS, 256>>>(attn, ath, atl);

    // 6) ctx = attn @ V  (B = V^T rows [d][s])
    {
        dim3 grd(DH / 64, SS / 128, BB * NH);
        gemm_sp<64,1><<<grd, 256, 61440>>>(ath, atl, VTh, VTl, nullptr,
                                           nullptr, ch, cl,
                                           SS, SS, SS, DM, 1.0f, NH,
                                           (long long)NH * SS * SS, (long long)SS * SS,
                                           (long long)NH * DH * SS, (long long)DH * SS,
                                           (long long)SS * DM, DH);
    }

    // 7) out = ctx @ W_o^T + b_o (fp32)
    {
        dim3 grd(DM / 128, MROWS / 128, 1);
        gemm_sp<128,0><<<grd, 256, 81920>>>(ch, cl, woh, wol, b_o,
                                            out, nullptr, nullptr,
                                            DM, DM, DM, DM, 1.0f, 1,
                                            0,0,0,0,0,0);
    }
}

// round 14
// speedup vs baseline: 2.0859x; 1.0293x over previous
#include <cuda_runtime.h>
#include <cuda_bf16.h>
#include <math.h>
#include <stdint.h>

#define BB 2
#define SS 2048
#define DM 768
#define NH 12
#define DH 64
#define MROWS (BB*SS)

static const long long OUT_ELEMS  = (long long)BB * SS * DM;            // 3,145,728
static const long long ATTN_ELEMS = (long long)BB * NH * SS * SS;       // 100,663,296

// ---------------------------------------------------------------------------
// Scratch (allocation-free rule: static __device__ arrays), bf16 hi/lo pairs.
// ---------------------------------------------------------------------------
__device__ __align__(16) unsigned short g_xqh[MROWS*DM], g_xql[MROWS*DM];
__device__ __align__(16) unsigned short g_xkh[MROWS*DM], g_xkl[MROWS*DM];
__device__ __align__(16) unsigned short g_xvh[MROWS*DM], g_xvl[MROWS*DM];
__device__ __align__(16) unsigned short g_wqh[DM*DM], g_wql[DM*DM];
__device__ __align__(16) unsigned short g_wkh[DM*DM], g_wkl[DM*DM];
__device__ __align__(16) unsigned short g_wvh[DM*DM], g_wvl[DM*DM];
__device__ __align__(16) unsigned short g_woh[DM*DM], g_wol[DM*DM];
__device__ __align__(16) unsigned short g_Qh[MROWS*DM], g_Ql[MROWS*DM];
__device__ __align__(16) unsigned short g_Kh[MROWS*DM], g_Kl[MROWS*DM];
__device__ __align__(16) unsigned short g_VTh[BB*NH*DH*SS], g_VTl[BB*NH*DH*SS]; // [(b,h,d)][s]
__device__ __align__(16) unsigned short g_ch[MROWS*DM], g_cl[MROWS*DM];
__device__ __align__(16) float g_attn_f[(long long)BB*NH*SS*SS];   // fallback if attn not in d_out

// ---------------------------------------------------------------------------
// helpers
// ---------------------------------------------------------------------------
__device__ __forceinline__ void cp16(uint32_t saddr, const void* gptr)
{
    asm volatile("cp.async.cg.shared.global [%0], [%1], 16;" :: "r"(saddr), "l"(gptr));
}

__device__ __forceinline__ void mma16816(float d[4], const uint32_t a[4], const uint32_t b[2])
{
    asm volatile(
        "mma.sync.aligned.m16n8k16.row.col.f32.bf16.bf16.f32 "
        "{%0,%1,%2,%3}, {%4,%5,%6,%7}, {%8,%9}, {%0,%1,%2,%3};"
        : "+f"(d[0]), "+f"(d[1]), "+f"(d[2]), "+f"(d[3])
        : "r"(a[0]), "r"(a[1]), "r"(a[2]), "r"(a[3]), "r"(b[0]), "r"(b[1]));
}

__device__ __forceinline__ unsigned short us(__nv_bfloat16 h) { return __bfloat16_as_ushort(h); }

__device__ __forceinline__ void store_split2(unsigned short* ph, unsigned short* pl,
                                             float x, float y)
{
    __nv_bfloat16 hx = __float2bfloat16_rn(x), hy = __float2bfloat16_rn(y);
    __nv_bfloat16 lx = __float2bfloat16_rn(x - __bfloat162float(hx));
    __nv_bfloat16 ly = __float2bfloat16_rn(y - __bfloat162float(hy));
    ushort2 hv; hv.x = us(hx); hv.y = us(hy);
    ushort2 lv; lv.x = us(lx); lv.y = us(ly);
    *(ushort2*)ph = hv; *(ushort2*)pl = lv;
}

__device__ __forceinline__ void store_split1(unsigned short* ph, unsigned short* pl, float x)
{
    __nv_bfloat16 hx = __float2bfloat16_rn(x);
    __nv_bfloat16 lx = __float2bfloat16_rn(x - __bfloat162float(hx));
    *ph = us(hx); *pl = us(lx);
}

__device__ __forceinline__ void pack4(float4 v, uint2& h, uint2& l)
{
    __nv_bfloat16 h0 = __float2bfloat16_rn(v.x), h1 = __float2bfloat16_rn(v.y);
    __nv_bfloat16 h2 = __float2bfloat16_rn(v.z), h3 = __float2bfloat16_rn(v.w);
    __nv_bfloat16 l0 = __float2bfloat16_rn(v.x - __bfloat162float(h0));
    __nv_bfloat16 l1 = __float2bfloat16_rn(v.y - __bfloat162float(h1));
    __nv_bfloat16 l2 = __float2bfloat16_rn(v.z - __bfloat162float(h2));
    __nv_bfloat16 l3 = __float2bfloat16_rn(v.w - __bfloat162float(h3));
    h.x = (uint32_t)us(h0) | ((uint32_t)us(h1) << 16);
    h.y = (uint32_t)us(h2) | ((uint32_t)us(h3) << 16);
    l.x = (uint32_t)us(l0) | ((uint32_t)us(l1) << 16);
    l.y = (uint32_t)us(l2) | ((uint32_t)us(l3) << 16);
}

// ---------------------------------------------------------------------------
// batched split: grid.y selects (src, dst) tuple; all tuples same n4.
// ---------------------------------------------------------------------------
__global__ void split_multi(const float4* __restrict__ s0, const float4* __restrict__ s1,
                            const float4* __restrict__ s2, const float4* __restrict__ s3,
                            uint2* h0, uint2* h1, uint2* h2, uint2* h3,
                            uint2* l0, uint2* l1, uint2* l2, uint2* l3,
                            int n4)
{
    const float4* ss[4] = { s0, s1, s2, s3 };
    uint2* hh[4] = { h0, h1, h2, h3 };
    uint2* ll[4] = { l0, l1, l2, l3 };
    int w = blockIdx.y;
    int i = blockIdx.x * blockDim.x + threadIdx.x;
    if (i >= n4) return;
    uint2 hp, lp;
    pack4(ss[w][i], hp, lp);
    hh[w][i] = hp; ll[w][i] = lp;
}

// ---------------------------------------------------------------------------
// Pre-split bf16 tensor-core GEMM (3-term):  C[m,n] = alpha*sum_k A[m,k]*B[n,k] + bias[n]
// BM=128, BN=128, BK=32, 256 threads, cp.async double-buffered.
// EPI: 0 = fp32 C, 1 = split hi/lo C, 2 = split hi/lo transposed (V^T layout).
// ---------------------------------------------------------------------------
template <int EPI>
__global__ __launch_bounds__(256, 2) void gemm_sp(
    const unsigned short* __restrict__ Ahg, const unsigned short* __restrict__ Alg,
    const unsigned short* __restrict__ Bhg, const unsigned short* __restrict__ Blg,
    const float* __restrict__ bias,
    float* __restrict__ Cf, unsigned short* __restrict__ Ch, unsigned short* __restrict__ Cl,
    int K, int lda, int ldb, int ldc, float alpha, int nh,
    long long sAb, long long sAh, long long sBb, long long sBh,
    long long sCb, long long sCh)
{
    constexpr int BM = 128, BN = 128;
    constexpr int WM = 2, WN = 4;
    constexpr int WTM = BM / WM, WTN = BN / WN;
    constexpr int TM = WTM / 16, TN = WTN / 8;
    constexpr int ROWU = 20;                 // 16 data u32 + 4 pad (80B stride)
    constexpr int ASZ = BM * ROWU;
    constexpr int BSZ = BN * ROWU;

    extern __shared__ uint32_t sm[];
    uint32_t* sAh_ = sm;
    uint32_t* sAl_ = sm + 2 * ASZ;
    uint32_t* sBh_ = sm + 4 * ASZ;
    uint32_t* sBl_ = sBh_ + 2 * BSZ;

    const int tid = threadIdx.x, lane = tid & 31, warp = tid >> 5;
    const int g = lane >> 2, t = lane & 3;
    const int wm = warp % WM, wn = warp / WM;
    const int wrow0 = wm * WTM, wcol0 = wn * WTN;

    const int zb = blockIdx.z / nh, zh = blockIdx.z % nh;
    const long long aoff = zb * sAb + zh * sAh;
    const long long boff = zb * sBb + zh * sBh;
    const long long coff = zb * sCb + zh * sCh;
    Ahg += aoff; Alg += aoff; Bhg += boff; Blg += boff;

    const int row0 = blockIdx.y * BM;
    const int col0 = blockIdx.x * BN;

    const uint32_t aAh = (uint32_t)__cvta_generic_to_shared(sAh_);
    const uint32_t aAl = (uint32_t)__cvta_generic_to_shared(sAl_);
    const uint32_t aBh = (uint32_t)__cvta_generic_to_shared(sBh_);
    const uint32_t aBl = (uint32_t)__cvta_generic_to_shared(sBl_);

    float acc[TM][TN][4] = {};
    const int KT = K / 32;

    auto load_slab = [&](int kt, int buf) {
        const int k0 = kt * 32;
        {
            int r = tid >> 1, c = tid & 1;
            long long go = (long long)(row0 + r) * lda + k0 + c * 16;
            uint32_t so = (uint32_t)(buf * ASZ + r * ROWU + c * 8) * 4u;
            cp16(aAh + so,      Ahg + go);
            cp16(aAh + so + 16, Ahg + go + 8);
            cp16(aAl + so,      Alg + go);
            cp16(aAl + so + 16, Alg + go + 8);
        }
        {
            int r = tid >> 1, c = tid & 1;
            long long go = (long long)(col0 + r) * ldb + k0 + c * 16;
            uint32_t so = (uint32_t)(buf * BSZ + r * ROWU + c * 8) * 4u;
            cp16(aBh + so,      Bhg + go);
            cp16(aBh + so + 16, Bhg + go + 8);
            cp16(aBl + so,      Blg + go);
            cp16(aBl + so + 16, Blg + go + 8);
        }
        asm volatile("cp.async.commit_group;" ::: "memory");
    };

    auto compute = [&](int buf) {
        const uint32_t* Abh = sAh_ + buf * ASZ;
        const uint32_t* Abl = sAl_ + buf * ASZ;
        const uint32_t* Bbh = sBh_ + buf * BSZ;
        const uint32_t* Bbl = sBl_ + buf * BSZ;
#pragma unroll
        for (int ks = 0; ks < 2; ++ks) {
            const int c = t + ks * 8;
            uint32_t bh[TN][2], bl[TN][2];
#pragma unroll
            for (int nt = 0; nt < TN; ++nt) {
                int n = wcol0 + nt * 8 + g;
                bh[nt][0] = Bbh[n * ROWU + c]; bh[nt][1] = Bbh[n * ROWU + c + 4];
                bl[nt][0] = Bbl[n * ROWU + c]; bl[nt][1] = Bbl[n * ROWU + c + 4];
            }
#pragma unroll
            for (int mt = 0; mt < TM; ++mt) {
                int m = wrow0 + mt * 16 + g;
                uint32_t ah[4] = { Abh[m*ROWU+c], Abh[(m+8)*ROWU+c],
                                   Abh[m*ROWU+c+4], Abh[(m+8)*ROWU+c+4] };
                uint32_t al[4] = { Abl[m*ROWU+c], Abl[(m+8)*ROWU+c],
                                   Abl[m*ROWU+c+4], Abl[(m+8)*ROWU+c+4] };
#pragma unroll
                for (int nt = 0; nt < TN; ++nt) {
                    mma16816(acc[mt][nt], ah, bh[nt]);
                    mma16816(acc[mt][nt], ah, bl[nt]);
                    mma16816(acc[mt][nt], al, bh[nt]);
                }
            }
        }
    };

    load_slab(0, 0);
    for (int kt = 0; kt < KT; ++kt) {
        if (kt + 1 < KT) {
            load_slab(kt + 1, (kt + 1) & 1);
            asm volatile("cp.async.wait_group 1;" ::: "memory");
        } else {
            asm volatile("cp.async.wait_group 0;" ::: "memory");
        }
        __syncthreads();
        compute(kt & 1);
        __syncthreads();
    }

#pragma unroll
    for (int mt = 0; mt < TM; ++mt) {
#pragma unroll
        for (int nt = 0; nt < TN; ++nt) {
            int m = row0 + wrow0 + mt * 16 + g;
            int n = col0 + wcol0 + nt * 8 + 2 * t;
            float b0 = 0.f, b1 = 0.f;
            if (bias) { b0 = bias[n]; b1 = bias[n + 1]; }
            float v00 = alpha * acc[mt][nt][0] + b0;
            float v01 = alpha * acc[mt][nt][1] + b1;
            float v10 = alpha * acc[mt][nt][2] + b0;
            float v11 = alpha * acc[mt][nt][3] + b1;
            if (EPI == 0) {
                float2 u0; u0.x = v00; u0.y = v01;
                float2 u1; u1.x = v10; u1.y = v11;
                *(float2*)&Cf[coff + (long long)m * ldc + n] = u0;
                *(float2*)&Cf[coff + (long long)(m + 8) * ldc + n] = u1;
            } else if (EPI == 1) {
                store_split2(Ch + coff + (long long)m * ldc + n,
                             Cl + coff + (long long)m * ldc + n, v00, v01);
                store_split2(Ch + coff + (long long)(m + 8) * ldc + n,
                             Cl + coff + (long long)(m + 8) * ldc + n, v10, v11);
            } else {
                // V^T layout: idx = ((b*NH + h)*64 + d)*SS + s, m=(b,s), n=(h,d)
                auto vt = [](int mm, int nn) -> long long {
                    int b = mm >> 11, s = mm & 2047, h = nn >> 6, d = nn & 63;
                    return (((long long)(b * NH + h) * DH + d) << 11) + s;
                };
                store_split1(Ch + vt(m, n),         Cl + vt(m, n),         v00);
                store_split1(Ch + vt(m, n + 1),     Cl + vt(m, n + 1),     v01);
                store_split1(Ch + vt(m + 8, n),     Cl + vt(m + 8, n),     v10);
                store_split1(Ch + vt(m + 8, n + 1), Cl + vt(m + 8, n + 1), v11);
            }
        }
    }
}

// ---------------------------------------------------------------------------
// AV GEMM: ctx = attn @ V.  A = fp32 attn (LDG float4 reg-staged, split to
// bf16 hi/lo at smem store). B = pre-split V^T (cp.async). C = ctx hi/lo.
// BM=128, BN=64, BK=32, 256 threads. Per (b,h) batch via blockIdx.z.
// ---------------------------------------------------------------------------
__global__ __launch_bounds__(256, 2) void gemm_av(
    const float* __restrict__ attn,
    const unsigned short* __restrict__ Bhg, const unsigned short* __restrict__ Blg,
    unsigned short* __restrict__ Ch, unsigned short* __restrict__ Cl)
{
    constexpr int BM = 128, BN = 64;
    constexpr int WM = 4, WN = 2;
    constexpr int WTM = BM / WM, WTN = BN / WN;   // 32, 32
    constexpr int TM = WTM / 16, TN = WTN / 8;    // 2, 4
    constexpr int ROWU = 20;
    constexpr int ASZ = BM * ROWU;                // 2560 u32
    constexpr int BSZ = BN * ROWU;                // 1280 u32

    extern __shared__ uint32_t sm[];
    uint32_t* sAh_ = sm;                          // [2][ASZ]
    uint32_t* sAl_ = sm + 2 * ASZ;
    uint32_t* sBh_ = sm + 4 * ASZ;
    uint32_t* sBl_ = sBh_ + 2 * BSZ;

    const int tid = threadIdx.x, lane = tid & 31, warp = tid >> 5;
    const int g = lane >> 2, t = lane & 3;
    const int wm = warp % WM, wn = warp / WM;
    const int wrow0 = wm * WTM, wcol0 = wn * WTN;

    const int z = blockIdx.z;                     // b*NH + h
    const int zb = z / NH, zh = z % NH;
    const long long aoff = (long long)z * SS * SS;
    const long long boff = (long long)z * DH * SS;
    const long long coff = (long long)zb * SS * DM + (long long)zh * DH;

    const int row0 = blockIdx.y * BM;

    const uint32_t aBh = (uint32_t)__cvta_generic_to_shared(sBh_);
    const uint32_t aBl = (uint32_t)__cvta_generic_to_shared(sBl_);

    float acc[TM][TN][4] = {};
    constexpr int KT = SS / 32;                   // 64
    float4 ra[4];

    auto loadAreg = [&](int kt) {
        const int k0 = kt * 32;
#pragma unroll
        for (int i = 0; i < 4; ++i) {
            int r = tid / 8 + i * 32;
            int c = (tid & 7) * 4;
            ra[i] = *(const float4*)&attn[aoff + (long long)(row0 + r) * SS + k0 + c];
        }
    };
    auto storeA = [&](int buf) {
#pragma unroll
        for (int i = 0; i < 4; ++i) {
            int r  = tid / 8 + i * 32;
            int cu = (tid & 7) * 2;
            uint2 hp, lp;
            pack4(ra[i], hp, lp);
            *(uint2*)&sAh_[buf * ASZ + r * ROWU + cu] = hp;
            *(uint2*)&sAl_[buf * ASZ + r * ROWU + cu] = lp;
        }
    };
    auto cpB = [&](int kt, int buf) {
        const int k0 = kt * 32;
        int r = (tid & 127) >> 1, c = tid & 1;
        long long go = (long long)r * SS + k0 + c * 16 + boff;
        uint32_t so = (uint32_t)(buf * BSZ + r * ROWU + c * 8) * 4u;
        if (tid < 128) {
            cp16(aBh + so,      Bhg + go);
            cp16(aBh + so + 16, Bhg + go + 8);
        } else {
            cp16(aBl + so,      Blg + go);
            cp16(aBl + so + 16, Blg + go + 8);
        }
        asm volatile("cp.async.commit_group;" ::: "memory");
    };
    auto compute = [&](int buf) {
        const uint32_t* Abh = sAh_ + buf * ASZ;
        const uint32_t* Abl = sAl_ + buf * ASZ;
        const uint32_t* Bbh = sBh_ + buf * BSZ;
        const uint32_t* Bbl = sBl_ + buf * BSZ;
#pragma unroll
        for (int ks = 0; ks < 2; ++ks) {
            const int c = t + ks * 8;
            uint32_t bh[TN][2], bl[TN][2];
#pragma unroll
            for (int nt = 0; nt < TN; ++nt) {
                int n = wcol0 + nt * 8 + g;
                bh[nt][0] = Bbh[n * ROWU + c]; bh[nt][1] = Bbh[n * ROWU + c + 4];
                bl[nt][0] = Bbl[n * ROWU + c]; bl[nt][1] = Bbl[n * ROWU + c + 4];
            }
#pragma unroll
            for (int mt = 0; mt < TM; ++mt) {
                int m = wrow0 + mt * 16 + g;
                uint32_t ah[4] = { Abh[m*ROWU+c], Abh[(m+8)*ROWU+c],
                                   Abh[m*ROWU+c+4], Abh[(m+8)*ROWU+c+4] };
                uint32_t al[4] = { Abl[m*ROWU+c], Abl[(m+8)*ROWU+c],
                                   Abl[m*ROWU+c+4], Abl[(m+8)*ROWU+c+4] };
#pragma unroll
                for (int nt = 0; nt < TN; ++nt) {
                    mma16816(acc[mt][nt], ah, bh[nt]);
                    mma16816(acc[mt][nt], ah, bl[nt]);
                    mma16816(acc[mt][nt], al, bh[nt]);
                }
            }
        }
    };

    // prologue
    loadAreg(0);
    cpB(0, 0);
    storeA(0);
    asm volatile("cp.async.wait_group 0;" ::: "memory");
    __syncthreads();

    for (int kt = 0; kt < KT; ++kt) {
        if (kt + 1 < KT) {
            loadAreg(kt + 1);              // overlaps with compute below
            cpB(kt + 1, (kt + 1) & 1);
        }
        compute(kt & 1);
        __syncthreads();                   // all reads of buf (kt+1)&1 (from kt-1) done
        if (kt + 1 < KT) {
            storeA((kt + 1) & 1);
            asm volatile("cp.async.wait_group 0;" ::: "memory");
            __syncthreads();
        }
    }

#pragma unroll
    for (int mt = 0; mt < TM; ++mt) {
#pragma unroll
        for (int nt = 0; nt < TN; ++nt) {
            int m = row0 + wrow0 + mt * 16 + g;
            int n = wcol0 + nt * 8 + 2 * t;
            store_split2(Ch + coff + (long long)m * DM + n,
                         Cl + coff + (long long)m * DM + n,
                         acc[mt][nt][0], acc[mt][nt][1]);
            store_split2(Ch + coff + (long long)(m + 8) * DM + n,
                         Cl + coff + (long long)(m + 8) * DM + n,
                         acc[mt][nt][2], acc[mt][nt][3]);
        }
    }
}

// ---------------------------------------------------------------------------
// Single-pass softmax: row (2048 fp32) in registers, one read + one fp32 write.
// ---------------------------------------------------------------------------
__global__ __launch_bounds__(256) void softmax_fused(float* __restrict__ attn)
{
    const long long row = blockIdx.x;
    float4* p4 = (float4*)(attn + (row << 11));
    const int t = threadIdx.x;
    __shared__ float red[256];

    float4 v[2];
    v[0] = p4[t];
    v[1] = p4[t + 256];

    float m = fmaxf(fmaxf(fmaxf(v[0].x, v[0].y), fmaxf(v[0].z, v[0].w)),
                    fmaxf(fmaxf(v[1].x, v[1].y), fmaxf(v[1].z, v[1].w)));
    red[t] = m; __syncthreads();
    for (int s = 128; s > 0; s >>= 1) {
        if (t < s) red[t] = fmaxf(red[t], red[t + s]);
        __syncthreads();
    }
    m = red[0]; __syncthreads();

    float sum = 0.f;
#pragma unroll
    for (int i = 0; i < 2; ++i) {
        v[i].x = __expf(v[i].x - m); v[i].y = __expf(v[i].y - m);
        v[i].z = __expf(v[i].z - m); v[i].w = __expf(v[i].w - m);
        sum += v[i].x + v[i].y + v[i].z + v[i].w;
    }
    red[t] = sum; __syncthreads();
    for (int s = 128; s > 0; s >>= 1) {
        if (t < s) red[t] += red[t + s];
        __syncthreads();
    }
    const float inv = 1.f / red[0];

#pragma unroll
    for (int i = 0; i < 2; ++i) {
        v[i].x *= inv; v[i].y *= inv; v[i].z *= inv; v[i].w *= inv;
        p4[t + i * 256] = v[i];
    }
}

// ---------------------------------------------------------------------------
extern "C" void kernel_launch(void* const* d_in, const int* in_sizes, int n_in,
                              void* d_out, int out_size)
{
    const float* query = (const float*)d_in[0];
    const float* key_  = (const float*)d_in[1];
    const float* value = (const float*)d_in[2];
    const float* W_q   = (const float*)d_in[3];
    const float* b_q   = (const float*)d_in[4];
    const float* W_k   = (const float*)d_in[5];
    const float* b_k   = (const float*)d_in[6];
    const float* W_v   = (const float*)d_in[7];
    const float* b_v   = (const float*)d_in[8];
    const float* W_o   = (const float*)d_in[9];
    const float* b_o   = (const float*)d_in[10];

    float* out = (float*)d_out;

    static bool inited = false;
    static unsigned short *xqh,*xql,*xkh,*xkl,*xvh,*xvl;
    static unsigned short *wqh,*wql,*wkh,*wkl,*wvh,*wvl,*woh,*wol;
    static unsigned short *Qh,*Ql,*Kh,*Kl,*VTh,*VTl,*ch,*cl;
    static float *attn_f;
    if (!inited) {
        inited = true;
        cudaGetSymbolAddress((void**)&xqh, g_xqh); cudaGetSymbolAddress((void**)&xql, g_xql);
        cudaGetSymbolAddress((void**)&xkh, g_xkh); cudaGetSymbolAddress((void**)&xkl, g_xkl);
        cudaGetSymbolAddress((void**)&xvh, g_xvh); cudaGetSymbolAddress((void**)&xvl, g_xvl);
        cudaGetSymbolAddress((void**)&wqh, g_wqh); cudaGetSymbolAddress((void**)&wql, g_wql);
        cudaGetSymbolAddress((void**)&wkh, g_wkh); cudaGetSymbolAddress((void**)&wkl, g_wkl);
        cudaGetSymbolAddress((void**)&wvh, g_wvh); cudaGetSymbolAddress((void**)&wvl, g_wvl);
        cudaGetSymbolAddress((void**)&woh, g_woh); cudaGetSymbolAddress((void**)&wol, g_wol);
        cudaGetSymbolAddress((void**)&Qh,  g_Qh);  cudaGetSymbolAddress((void**)&Ql,  g_Ql);
        cudaGetSymbolAddress((void**)&Kh,  g_Kh);  cudaGetSymbolAddress((void**)&Kl,  g_Kl);
        cudaGetSymbolAddress((void**)&VTh, g_VTh); cudaGetSymbolAddress((void**)&VTl, g_VTl);
        cudaGetSymbolAddress((void**)&ch,  g_ch);  cudaGetSymbolAddress((void**)&cl,  g_cl);
        cudaGetSymbolAddress((void**)&attn_f, g_attn_f);
        cudaFuncSetAttribute(gemm_sp<0>, cudaFuncAttributeMaxDynamicSharedMemorySize, 81920);
        cudaFuncSetAttribute(gemm_sp<1>, cudaFuncAttributeMaxDynamicSharedMemorySize, 81920);
        cudaFuncSetAttribute(gemm_sp<2>, cudaFuncAttributeMaxDynamicSharedMemorySize, 81920);
        cudaFuncSetAttribute(gemm_av,    cudaFuncAttributeMaxDynamicSharedMemorySize, 61440);
    }

    float* attn = attn_f;
    if ((long long)out_size >= OUT_ELEMS + ATTN_ELEMS)
        attn = out + OUT_ELEMS;

    // 0) split raw inputs (3) + weights (4) to bf16 hi/lo — two batched launches
    {
        int n4i = MROWS * DM / 4;     // 786432
        int n4w = DM * DM / 4;        // 147456
        dim3 gi((n4i + 255) / 256, 3);
        split_multi<<<gi, 256>>>((const float4*)query, (const float4*)key_,
                                 (const float4*)value, (const float4*)value,
                                 (uint2*)xqh, (uint2*)xkh, (uint2*)xvh, (uint2*)xvh,
                                 (uint2*)xql, (uint2*)xkl, (uint2*)xvl, (uint2*)xvl,
                                 n4i);
        dim3 gw((n4w + 255) / 256, 4);
        split_multi<<<gw, 256>>>((const float4*)W_q, (const float4*)W_k,
                                 (const float4*)W_v, (const float4*)W_o,
                                 (uint2*)wqh, (uint2*)wkh, (uint2*)wvh, (uint2*)woh,
                                 (uint2*)wql, (uint2*)wkl, (uint2*)wvl, (uint2*)wol,
                                 n4w);
    }

    // 1-3) projections: Q,K split row-major; V split transposed (V^T per head)
    {
        dim3 grd(DM / 128, MROWS / 128, 1);
        gemm_sp<1><<<grd, 256, 81920>>>(xqh, xql, wqh, wql, b_q,
                                        nullptr, Qh, Ql,
                                        DM, DM, DM, DM, 1.0f, 1,
                                        0,0,0,0,0,0);
        gemm_sp<1><<<grd, 256, 81920>>>(xkh, xkl, wkh, wkl, b_k,
                                        nullptr, Kh, Kl,
                                        DM, DM, DM, DM, 1.0f, 1,
                                        0,0,0,0,0,0);
        gemm_sp<2><<<grd, 256, 81920>>>(xvh, xvl, wvh, wvl, b_v,
                                        nullptr, VTh, VTl,
                                        DM, DM, DM, 0, 1.0f, 1,
                                        0,0,0,0,0,0);
    }

    // 4) scores = (Q.K)/8 -> attn (fp32)
    {
        dim3 grd(SS / 128, SS / 128, BB * NH);
        gemm_sp<0><<<grd, 256, 81920>>>(Qh, Ql, Kh, Kl, nullptr,
                                        attn, nullptr, nullptr,
                                        DH, DM, DM, SS, 0.125f, NH,
                                        (long long)SS * DM, DH,
                                        (long long)SS * DM, DH,
                                        (long long)NH * SS * SS, (long long)SS * SS);
    }

    // 5) single-pass softmax: fp32 in-place (normalized probs are the output)
    softmax_fused<<<BB * NH * SS, 256>>>(attn);

    // 6) ctx = attn(fp32) @ V  (split A in-kernel; B = V^T hi/lo)
    {
        dim3 grd(1, SS / 128, BB * NH);
        gemm_av<<<grd, 256, 61440>>>(attn, VTh, VTl, ch, cl);
    }

    // 7) out = ctx @ W_o^T + b_o (fp32)
    {
        dim3 grd(DM / 128, MROWS / 128, 1);
        gemm_sp<0><<<grd, 256, 81920>>>(ch, cl, woh, wol, b_o,
                                        out, nullptr, nullptr,
                                        DM, DM, DM, DM, 1.0f, 1,
                                        0,0,0,0,0,0);
    }
}

// round 16
// speedup vs baseline: 2.4845x; 1.1911x over previous
#include <cuda_runtime.h>
#include <cuda_bf16.h>
#include <math.h>
#include <stdint.h>

#define BB 2
#define SS 2048
#define DM 768
#define NH 12
#define DH 64
#define MROWS (BB*SS)
#define NZ (BB*NH)

static const long long OUT_ELEMS  = (long long)BB * SS * DM;            // 3,145,728
static const long long ATTN_ELEMS = (long long)BB * NH * SS * SS;       // 100,663,296

// ---------------------------------------------------------------------------
// Scratch (allocation-free rule: static __device__ arrays)
// ---------------------------------------------------------------------------
__device__ __align__(16) unsigned short g_xqh[MROWS*DM], g_xql[MROWS*DM];
__device__ __align__(16) unsigned short g_xkh[MROWS*DM], g_xkl[MROWS*DM];
__device__ __align__(16) unsigned short g_xvh[MROWS*DM], g_xvl[MROWS*DM];
__device__ __align__(16) unsigned short g_wqh[DM*DM], g_wql[DM*DM];
__device__ __align__(16) unsigned short g_wkh[DM*DM], g_wkl[DM*DM];
__device__ __align__(16) unsigned short g_wvh[DM*DM], g_wvl[DM*DM];
__device__ __align__(16) unsigned short g_woh[DM*DM], g_wol[DM*DM];
__device__ __align__(16) unsigned short g_Qh[MROWS*DM], g_Ql[MROWS*DM];
__device__ __align__(16) unsigned short g_Kh[MROWS*DM], g_Kl[MROWS*DM];
__device__ __align__(16) unsigned short g_VTh[NZ*DH*SS], g_VTl[NZ*DH*SS]; // [(b,h,d)][s]
__device__ __align__(16) unsigned short g_ch[MROWS*DM], g_cl[MROWS*DM];
__device__ __align__(16) float g_stats[(long long)NZ*SS*64*2];   // per (z,row,coltile32): (max, expsum)
__device__ __align__(16) float g_rstats[(long long)NZ*SS*2];     // per (z,row): (M, 1/sum)
__device__ __align__(16) float g_attn_f[(long long)NZ*SS*SS];    // fallback if attn not in d_out

// ---------------------------------------------------------------------------
// helpers
// ---------------------------------------------------------------------------
__device__ __forceinline__ void cp16(uint32_t saddr, const void* gptr)
{
    asm volatile("cp.async.cg.shared.global [%0], [%1], 16;" :: "r"(saddr), "l"(gptr));
}

__device__ __forceinline__ void mma16816(float d[4], const uint32_t a[4], const uint32_t b[2])
{
    asm volatile(
        "mma.sync.aligned.m16n8k16.row.col.f32.bf16.bf16.f32 "
        "{%0,%1,%2,%3}, {%4,%5,%6,%7}, {%8,%9}, {%0,%1,%2,%3};"
        : "+f"(d[0]), "+f"(d[1]), "+f"(d[2]), "+f"(d[3])
        : "r"(a[0]), "r"(a[1]), "r"(a[2]), "r"(a[3]), "r"(b[0]), "r"(b[1]));
}

__device__ __forceinline__ unsigned short us(__nv_bfloat16 h) { return __bfloat16_as_ushort(h); }

__device__ __forceinline__ void store_split2(unsigned short* ph, unsigned short* pl,
                                             float x, float y)
{
    __nv_bfloat16 hx = __float2bfloat16_rn(x), hy = __float2bfloat16_rn(y);
    __nv_bfloat16 lx = __float2bfloat16_rn(x - __bfloat162float(hx));
    __nv_bfloat16 ly = __float2bfloat16_rn(y - __bfloat162float(hy));
    ushort2 hv; hv.x = us(hx); hv.y = us(hy);
    ushort2 lv; lv.x = us(lx); lv.y = us(ly);
    *(ushort2*)ph = hv; *(ushort2*)pl = lv;
}

__device__ __forceinline__ void store_split1(unsigned short* ph, unsigned short* pl, float x)
{
    __nv_bfloat16 hx = __float2bfloat16_rn(x);
    __nv_bfloat16 lx = __float2bfloat16_rn(x - __bfloat162float(hx));
    *ph = us(hx); *pl = us(lx);
}

__device__ __forceinline__ void pack4(float4 v, uint2& h, uint2& l)
{
    __nv_bfloat16 h0 = __float2bfloat16_rn(v.x), h1 = __float2bfloat16_rn(v.y);
    __nv_bfloat16 h2 = __float2bfloat16_rn(v.z), h3 = __float2bfloat16_rn(v.w);
    __nv_bfloat16 l0 = __float2bfloat16_rn(v.x - __bfloat162float(h0));
    __nv_bfloat16 l1 = __float2bfloat16_rn(v.y - __bfloat162float(h1));
    __nv_bfloat16 l2 = __float2bfloat16_rn(v.z - __bfloat162float(h2));
    __nv_bfloat16 l3 = __float2bfloat16_rn(v.w - __bfloat162float(h3));
    h.x = (uint32_t)us(h0) | ((uint32_t)us(h1) << 16);
    h.y = (uint32_t)us(h2) | ((uint32_t)us(h3) << 16);
    l.x = (uint32_t)us(l0) | ((uint32_t)us(l1) << 16);
    l.y = (uint32_t)us(l2) | ((uint32_t)us(l3) << 16);
}

// ---------------------------------------------------------------------------
// batched split: grid.y selects (src, dst) tuple; all tuples same n4.
// ---------------------------------------------------------------------------
__global__ void split_multi(const float4* __restrict__ s0, const float4* __restrict__ s1,
                            const float4* __restrict__ s2, const float4* __restrict__ s3,
                            uint2* h0, uint2* h1, uint2* h2, uint2* h3,
                            uint2* l0, uint2* l1, uint2* l2, uint2* l3,
                            int n4)
{
    const float4* ss[4] = { s0, s1, s2, s3 };
    uint2* hh[4] = { h0, h1, h2, h3 };
    uint2* ll[4] = { l0, l1, l2, l3 };
    int w = blockIdx.y;
    int i = blockIdx.x * blockDim.x + threadIdx.x;
    if (i >= n4) return;
    uint2 hp, lp;
    pack4(ss[w][i], hp, lp);
    hh[w][i] = hp; ll[w][i] = lp;
}

// ===========================================================================
// Merged QKV projection GEMM. blockIdx.z in {0,1,2} selects (X, W, b, dst).
// z<2: C split hi/lo row-major. z==2: V split hi/lo transposed (V^T layout).
// M=4096, N=768, K=768. BM=BN=128, BK=32, 256 thr, cp.async double-buffered.
// ===========================================================================
__global__ __launch_bounds__(256, 2) void gemm_qkv(
    const unsigned short* __restrict__ xqh_, const unsigned short* __restrict__ xql_,
    const unsigned short* __restrict__ xkh_, const unsigned short* __restrict__ xkl_,
    const unsigned short* __restrict__ xvh_, const unsigned short* __restrict__ xvl_,
    const unsigned short* __restrict__ wqh_, const unsigned short* __restrict__ wql_,
    const unsigned short* __restrict__ wkh_, const unsigned short* __restrict__ wkl_,
    const unsigned short* __restrict__ wvh_, const unsigned short* __restrict__ wvl_,
    const float* __restrict__ b_q, const float* __restrict__ b_k, const float* __restrict__ b_v,
    unsigned short* __restrict__ Qh_, unsigned short* __restrict__ Ql_,
    unsigned short* __restrict__ Kh_, unsigned short* __restrict__ Kl_,
    unsigned short* __restrict__ VTh_, unsigned short* __restrict__ VTl_)
{
    constexpr int BM = 128, BN = 128;
    constexpr int WM = 2, WN = 4;
    constexpr int WTM = BM / WM, WTN = BN / WN;
    constexpr int TM = WTM / 16, TN = WTN / 8;
    constexpr int ROWU = 20;
    constexpr int ASZ = BM * ROWU, BSZ = BN * ROWU;

    extern __shared__ uint32_t sm[];
    uint32_t* sAh_ = sm;
    uint32_t* sAl_ = sm + 2 * ASZ;
    uint32_t* sBh_ = sm + 4 * ASZ;
    uint32_t* sBl_ = sBh_ + 2 * BSZ;

    const int tid = threadIdx.x, lane = tid & 31, warp = tid >> 5;
    const int g = lane >> 2, t = lane & 3;
    const int wm = warp % WM, wn = warp / WM;
    const int wrow0 = wm * WTM, wcol0 = wn * WTN;

    const int z = blockIdx.z;
    const unsigned short *Ahg, *Alg, *Bhg, *Blg;
    const float* bias;
    if (z == 0)      { Ahg = xqh_; Alg = xql_; Bhg = wqh_; Blg = wql_; bias = b_q; }
    else if (z == 1) { Ahg = xkh_; Alg = xkl_; Bhg = wkh_; Blg = wkl_; bias = b_k; }
    else             { Ahg = xvh_; Alg = xvl_; Bhg = wvh_; Blg = wvl_; bias = b_v; }

    const int row0 = blockIdx.y * BM;
    const int col0 = blockIdx.x * BN;

    const uint32_t aAh = (uint32_t)__cvta_generic_to_shared(sAh_);
    const uint32_t aAl = (uint32_t)__cvta_generic_to_shared(sAl_);
    const uint32_t aBh = (uint32_t)__cvta_generic_to_shared(sBh_);
    const uint32_t aBl = (uint32_t)__cvta_generic_to_shared(sBl_);

    float acc[TM][TN][4] = {};
    constexpr int KT = DM / 32;  // 24

    auto load_slab = [&](int kt, int buf) {
        const int k0 = kt * 32;
        {
            int r = tid >> 1, c = tid & 1;
            long long go = (long long)(row0 + r) * DM + k0 + c * 16;
            uint32_t so = (uint32_t)(buf * ASZ + r * ROWU + c * 8) * 4u;
            cp16(aAh + so,      Ahg + go);
            cp16(aAh + so + 16, Ahg + go + 8);
            cp16(aAl + so,      Alg + go);
            cp16(aAl + so + 16, Alg + go + 8);
        }
        {
            int r = tid >> 1, c = tid & 1;
            long long go = (long long)(col0 + r) * DM + k0 + c * 16;
            uint32_t so = (uint32_t)(buf * BSZ + r * ROWU + c * 8) * 4u;
            cp16(aBh + so,      Bhg + go);
            cp16(aBh + so + 16, Bhg + go + 8);
            cp16(aBl + so,      Blg + go);
            cp16(aBl + so + 16, Blg + go + 8);
        }
        asm volatile("cp.async.commit_group;" ::: "memory");
    };

    auto compute = [&](int buf) {
        const uint32_t* Abh = sAh_ + buf * ASZ;
        const uint32_t* Abl = sAl_ + buf * ASZ;
        const uint32_t* Bbh = sBh_ + buf * BSZ;
        const uint32_t* Bbl = sBl_ + buf * BSZ;
#pragma unroll
        for (int ks = 0; ks < 2; ++ks) {
            const int c = t + ks * 8;
            uint32_t bh[TN][2], bl[TN][2];
#pragma unroll
            for (int nt = 0; nt < TN; ++nt) {
                int n = wcol0 + nt * 8 + g;
                bh[nt][0] = Bbh[n * ROWU + c]; bh[nt][1] = Bbh[n * ROWU + c + 4];
                bl[nt][0] = Bbl[n * ROWU + c]; bl[nt][1] = Bbl[n * ROWU + c + 4];
            }
#pragma unroll
            for (int mt = 0; mt < TM; ++mt) {
                int m = wrow0 + mt * 16 + g;
                uint32_t ah[4] = { Abh[m*ROWU+c], Abh[(m+8)*ROWU+c],
                                   Abh[m*ROWU+c+4], Abh[(m+8)*ROWU+c+4] };
                uint32_t al[4] = { Abl[m*ROWU+c], Abl[(m+8)*ROWU+c],
                                   Abl[m*ROWU+c+4], Abl[(m+8)*ROWU+c+4] };
#pragma unroll
                for (int nt = 0; nt < TN; ++nt) {
                    mma16816(acc[mt][nt], ah, bh[nt]);
                    mma16816(acc[mt][nt], ah, bl[nt]);
                    mma16816(acc[mt][nt], al, bh[nt]);
                }
            }
        }
    };

    load_slab(0, 0);
    for (int kt = 0; kt < KT; ++kt) {
        if (kt + 1 < KT) {
            load_slab(kt + 1, (kt + 1) & 1);
            asm volatile("cp.async.wait_group 1;" ::: "memory");
        } else {
            asm volatile("cp.async.wait_group 0;" ::: "memory");
        }
        __syncthreads();
        compute(kt & 1);
        __syncthreads();
    }

#pragma unroll
    for (int mt = 0; mt < TM; ++mt) {
#pragma unroll
        for (int nt = 0; nt < TN; ++nt) {
            int m = row0 + wrow0 + mt * 16 + g;
            int n = col0 + wcol0 + nt * 8 + 2 * t;
            float b0 = bias[n], b1 = bias[n + 1];
            float v00 = acc[mt][nt][0] + b0;
            float v01 = acc[mt][nt][1] + b1;
            float v10 = acc[mt][nt][2] + b0;
            float v11 = acc[mt][nt][3] + b1;
            if (z < 2) {
                unsigned short* Ch = (z == 0) ? Qh_ : Kh_;
                unsigned short* Cl = (z == 0) ? Ql_ : Kl_;
                store_split2(Ch + (long long)m * DM + n, Cl + (long long)m * DM + n, v00, v01);
                store_split2(Ch + (long long)(m + 8) * DM + n, Cl + (long long)(m + 8) * DM + n, v10, v11);
            } else {
                auto vt = [](int mm, int nn) -> long long {
                    int b = mm >> 11, s = mm & 2047, h = nn >> 6, d = nn & 63;
                    return (((long long)(b * NH + h) * DH + d) << 11) + s;
                };
                store_split1(VTh_ + vt(m, n),         VTl_ + vt(m, n),         v00);
                store_split1(VTh_ + vt(m, n + 1),     VTl_ + vt(m, n + 1),     v01);
                store_split1(VTh_ + vt(m + 8, n),     VTl_ + vt(m + 8, n),     v10);
                store_split1(VTh_ + vt(m + 8, n + 1), VTl_ + vt(m + 8, n + 1), v11);
            }
        }
    }
}

// ===========================================================================
// Generic pre-split GEMM. EPI: 0 = fp32 C (+bias). 3 = fp32 C + softmax stats
// (per row, per 32-col warp tile: max + sum(exp(v-max))).
// ===========================================================================
template <int EPI>
__global__ __launch_bounds__(256, 2) void gemm_sp(
    const unsigned short* __restrict__ Ahg, const unsigned short* __restrict__ Alg,
    const unsigned short* __restrict__ Bhg, const unsigned short* __restrict__ Blg,
    const float* __restrict__ bias,
    float* __restrict__ Cf, float* __restrict__ stats,
    int K, int lda, int ldb, int ldc, float alpha, int nh,
    long long sAb, long long sAh, long long sBb, long long sBh,
    long long sCb, long long sCh)
{
    constexpr int BM = 128, BN = 128;
    constexpr int WM = 2, WN = 4;
    constexpr int WTM = BM / WM, WTN = BN / WN;
    constexpr int TM = WTM / 16, TN = WTN / 8;
    constexpr int ROWU = 20;
    constexpr int ASZ = BM * ROWU, BSZ = BN * ROWU;

    extern __shared__ uint32_t sm[];
    uint32_t* sAh_ = sm;
    uint32_t* sAl_ = sm + 2 * ASZ;
    uint32_t* sBh_ = sm + 4 * ASZ;
    uint32_t* sBl_ = sBh_ + 2 * BSZ;

    const int tid = threadIdx.x, lane = tid & 31, warp = tid >> 5;
    const int g = lane >> 2, t = lane & 3;
    const int wm = warp % WM, wn = warp / WM;
    const int wrow0 = wm * WTM, wcol0 = wn * WTN;

    const int zb = blockIdx.z / nh, zh = blockIdx.z % nh;
    const long long aoff = zb * sAb + zh * sAh;
    const long long boff = zb * sBb + zh * sBh;
    const long long coff = zb * sCb + zh * sCh;
    Ahg += aoff; Alg += aoff; Bhg += boff; Blg += boff;

    const int row0 = blockIdx.y * BM;
    const int col0 = blockIdx.x * BN;

    const uint32_t aAh = (uint32_t)__cvta_generic_to_shared(sAh_);
    const uint32_t aAl = (uint32_t)__cvta_generic_to_shared(sAl_);
    const uint32_t aBh = (uint32_t)__cvta_generic_to_shared(sBh_);
    const uint32_t aBl = (uint32_t)__cvta_generic_to_shared(sBl_);

    float acc[TM][TN][4] = {};
    const int KT = K / 32;

    auto load_slab = [&](int kt, int buf) {
        const int k0 = kt * 32;
        {
            int r = tid >> 1, c = tid & 1;
            long long go = (long long)(row0 + r) * lda + k0 + c * 16;
            uint32_t so = (uint32_t)(buf * ASZ + r * ROWU + c * 8) * 4u;
            cp16(aAh + so,      Ahg + go);
            cp16(aAh + so + 16, Ahg + go + 8);
            cp16(aAl + so,      Alg + go);
            cp16(aAl + so + 16, Alg + go + 8);
        }
        {
            int r = tid >> 1, c = tid & 1;
            long long go = (long long)(col0 + r) * ldb + k0 + c * 16;
            uint32_t so = (uint32_t)(buf * BSZ + r * ROWU + c * 8) * 4u;
            cp16(aBh + so,      Bhg + go);
            cp16(aBh + so + 16, Bhg + go + 8);
            cp16(aBl + so,      Blg + go);
            cp16(aBl + so + 16, Blg + go + 8);
        }
        asm volatile("cp.async.commit_group;" ::: "memory");
    };

    auto compute = [&](int buf) {
        const uint32_t* Abh = sAh_ + buf * ASZ;
        const uint32_t* Abl = sAl_ + buf * ASZ;
        const uint32_t* Bbh = sBh_ + buf * BSZ;
        const uint32_t* Bbl = sBl_ + buf * BSZ;
#pragma unroll
        for (int ks = 0; ks < 2; ++ks) {
            const int c = t + ks * 8;
            uint32_t bh[TN][2], bl[TN][2];
#pragma unroll
            for (int nt = 0; nt < TN; ++nt) {
                int n = wcol0 + nt * 8 + g;
                bh[nt][0] = Bbh[n * ROWU + c]; bh[nt][1] = Bbh[n * ROWU + c + 4];
                bl[nt][0] = Bbl[n * ROWU + c]; bl[nt][1] = Bbl[n * ROWU + c + 4];
            }
#pragma unroll
            for (int mt = 0; mt < TM; ++mt) {
                int m = wrow0 + mt * 16 + g;
                uint32_t ah[4] = { Abh[m*ROWU+c], Abh[(m+8)*ROWU+c],
                                   Abh[m*ROWU+c+4], Abh[(m+8)*ROWU+c+4] };
                uint32_t al[4] = { Abl[m*ROWU+c], Abl[(m+8)*ROWU+c],
                                   Abl[m*ROWU+c+4], Abl[(m+8)*ROWU+c+4] };
#pragma unroll
                for (int nt = 0; nt < TN; ++nt) {
                    mma16816(acc[mt][nt], ah, bh[nt]);
                    mma16816(acc[mt][nt], ah, bl[nt]);
                    mma16816(acc[mt][nt], al, bh[nt]);
                }
            }
        }
    };

    load_slab(0, 0);
    for (int kt = 0; kt < KT; ++kt) {
        if (kt + 1 < KT) {
            load_slab(kt + 1, (kt + 1) & 1);
            asm volatile("cp.async.wait_group 1;" ::: "memory");
        } else {
            asm volatile("cp.async.wait_group 0;" ::: "memory");
        }
        __syncthreads();
        compute(kt & 1);
        __syncthreads();
    }

#pragma unroll
    for (int mt = 0; mt < TM; ++mt) {
        float va[2 * TN], vb[2 * TN];
#pragma unroll
        for (int nt = 0; nt < TN; ++nt) {
            int m = row0 + wrow0 + mt * 16 + g;
            int n = col0 + wcol0 + nt * 8 + 2 * t;
            float b0 = 0.f, b1 = 0.f;
            if (EPI == 0 && bias) { b0 = bias[n]; b1 = bias[n + 1]; }
            va[2*nt]   = alpha * acc[mt][nt][0] + b0;
            va[2*nt+1] = alpha * acc[mt][nt][1] + b1;
            vb[2*nt]   = alpha * acc[mt][nt][2] + b0;
            vb[2*nt+1] = alpha * acc[mt][nt][3] + b1;
            float2 u0; u0.x = va[2*nt]; u0.y = va[2*nt+1];
            float2 u1; u1.x = vb[2*nt]; u1.y = vb[2*nt+1];
            *(float2*)&Cf[coff + (long long)m * ldc + n] = u0;
            *(float2*)&Cf[coff + (long long)(m + 8) * ldc + n] = u1;
        }
        if (EPI == 3) {
            // per-row (32-col warp tile) max + expsum via quad shuffles
            float mx0 = va[0], mx1 = vb[0];
#pragma unroll
            for (int j = 1; j < 2 * TN; ++j) { mx0 = fmaxf(mx0, va[j]); mx1 = fmaxf(mx1, vb[j]); }
            mx0 = fmaxf(mx0, __shfl_xor_sync(0xffffffffu, mx0, 1));
            mx0 = fmaxf(mx0, __shfl_xor_sync(0xffffffffu, mx0, 2));
            mx1 = fmaxf(mx1, __shfl_xor_sync(0xffffffffu, mx1, 1));
            mx1 = fmaxf(mx1, __shfl_xor_sync(0xffffffffu, mx1, 2));
            float s0 = 0.f, s1 = 0.f;
#pragma unroll
            for (int j = 0; j < 2 * TN; ++j) { s0 += __expf(va[j] - mx0); s1 += __expf(vb[j] - mx1); }
            s0 += __shfl_xor_sync(0xffffffffu, s0, 1);
            s0 += __shfl_xor_sync(0xffffffffu, s0, 2);
            s1 += __shfl_xor_sync(0xffffffffu, s1, 1);
            s1 += __shfl_xor_sync(0xffffffffu, s1, 2);
            if (t == 0) {
                int m  = row0 + wrow0 + mt * 16 + g;
                int ct = (col0 + wcol0) >> 5;
                long long si0 = ((((long long)blockIdx.z << 11) + m)     * 64 + ct) * 2;
                long long si1 = ((((long long)blockIdx.z << 11) + m + 8) * 64 + ct) * 2;
                float2 p0; p0.x = mx0; p0.y = s0;
                float2 p1; p1.x = mx1; p1.y = s1;
                *(float2*)&stats[si0] = p0;
                *(float2*)&stats[si1] = p1;
            }
        }
    }
}

// ---------------------------------------------------------------------------
// Row stats reduce: per row, merge 64 (max, expsum) tiles -> (M, 1/sum).
// One warp per row, 8 rows per block.
// ---------------------------------------------------------------------------
__global__ __launch_bounds__(256) void rowstats_reduce(const float* __restrict__ stats,
                                                       float* __restrict__ rstats)
{
    const int warp = threadIdx.x >> 5, lane = threadIdx.x & 31;
    const long long row = (long long)blockIdx.x * 8 + warp;      // 0 .. NZ*SS-1
    const float2* sp = (const float2*)(stats + row * 64 * 2);
    float2 a = sp[lane], b = sp[lane + 32];
    float M = fmaxf(a.x, b.x);
    float S = a.y * __expf(a.x - M) + b.y * __expf(b.x - M);
#pragma unroll
    for (int d = 16; d > 0; d >>= 1) {
        float Mo = __shfl_xor_sync(0xffffffffu, M, d);
        float So = __shfl_xor_sync(0xffffffffu, S, d);
        float Mn = fmaxf(M, Mo);
        S = S * __expf(M - Mn) + So * __expf(Mo - Mn);
        M = Mn;
    }
    if (lane == 0) {
        float2 r; r.x = M; r.y = 1.f / S;
        *(float2*)&rstats[row * 2] = r;
    }
}

// ---------------------------------------------------------------------------
// AV GEMM with fused softmax: A = RAW scores fp32; apply exp(s-M)*inv in-reg,
// optionally write normalized probs back to attn; split to hi/lo for mma.
// B = pre-split V^T. BM=128, BN=64, BK=32, 256 thr.
// ---------------------------------------------------------------------------
__global__ __launch_bounds__(256, 2) void gemm_av(
    const float* __restrict__ attn_in, float* __restrict__ attn_out,
    const float* __restrict__ rstats,
    const unsigned short* __restrict__ Bhg, const unsigned short* __restrict__ Blg,
    unsigned short* __restrict__ Ch, unsigned short* __restrict__ Cl,
    int write_attn)
{
    constexpr int BM = 128, BN = 64;
    constexpr int WM = 4, WN = 2;
    constexpr int WTM = BM / WM, WTN = BN / WN;   // 32, 32
    constexpr int TM = WTM / 16, TN = WTN / 8;    // 2, 4
    constexpr int ROWU = 20;
    constexpr int ASZ = BM * ROWU, BSZ = BN * ROWU;

    extern __shared__ uint32_t sm[];
    uint32_t* sAh_ = sm;
    uint32_t* sAl_ = sm + 2 * ASZ;
    uint32_t* sBh_ = sm + 4 * ASZ;
    uint32_t* sBl_ = sBh_ + 2 * BSZ;

    const int tid = threadIdx.x, lane = tid & 31, warp = tid >> 5;
    const int g = lane >> 2, t = lane & 3;
    const int wm = warp % WM, wn = warp / WM;
    const int wrow0 = wm * WTM, wcol0 = wn * WTN;

    const int z = blockIdx.z;
    const int zb = z / NH, zh = z % NH;
    const long long aoff = (long long)z * SS * SS;
    const long long boff = (long long)z * DH * SS;
    const long long coff = (long long)zb * SS * DM + (long long)zh * DH;

    const int row0 = blockIdx.y * BM;

    const uint32_t aBh = (uint32_t)__cvta_generic_to_shared(sBh_);
    const uint32_t aBl = (uint32_t)__cvta_generic_to_shared(sBl_);

    float acc[TM][TN][4] = {};
    constexpr int KT = SS / 32;                   // 64
    float4 ra[4];

    // per-thread row softmax stats (constant over slabs)
    float2 st[4];
#pragma unroll
    for (int i = 0; i < 4; ++i)
        st[i] = ((const float2*)rstats)[((long long)z << 11) + row0 + tid / 8 + i * 32];

    auto loadAreg = [&](int kt) {
        const int k0 = kt * 32;
#pragma unroll
        for (int i = 0; i < 4; ++i) {
            int r = tid / 8 + i * 32;
            int c = (tid & 7) * 4;
            ra[i] = *(const float4*)&attn_in[aoff + (long long)(row0 + r) * SS + k0 + c];
        }
    };
    auto storeA = [&](int buf, int kt) {
        const int k0 = kt * 32;
#pragma unroll
        for (int i = 0; i < 4; ++i) {
            int r  = tid / 8 + i * 32;
            int cu = (tid & 7) * 2;
            float4 v = ra[i];
            v.x = __expf(v.x - st[i].x) * st[i].y;
            v.y = __expf(v.y - st[i].x) * st[i].y;
            v.z = __expf(v.z - st[i].x) * st[i].y;
            v.w = __expf(v.w - st[i].x) * st[i].y;
            if (write_attn) {
                int c = (tid & 7) * 4;
                *(float4*)&attn_out[aoff + (long long)(row0 + r) * SS + k0 + c] = v;
            }
            uint2 hp, lp;
            pack4(v, hp, lp);
            *(uint2*)&sAh_[buf * ASZ + r * ROWU + cu] = hp;
            *(uint2*)&sAl_[buf * ASZ + r * ROWU + cu] = lp;
        }
    };
    auto cpB = [&](int kt, int buf) {
        const int k0 = kt * 32;
        int r = (tid & 127) >> 1, c = tid & 1;
        long long go = (long long)r * SS + k0 + c * 16 + boff;
        uint32_t so = (uint32_t)(buf * BSZ + r * ROWU + c * 8) * 4u;
        if (tid < 128) {
            cp16(aBh + so,      Bhg + go);
            cp16(aBh + so + 16, Bhg + go + 8);
        } else {
            cp16(aBl + so,      Blg + go);
            cp16(aBl + so + 16, Blg + go + 8);
        }
        asm volatile("cp.async.commit_group;" ::: "memory");
    };
    auto compute = [&](int buf) {
        const uint32_t* Abh = sAh_ + buf * ASZ;
        const uint32_t* Abl = sAl_ + buf * ASZ;
        const uint32_t* Bbh = sBh_ + buf * BSZ;
        const uint32_t* Bbl = sBl_ + buf * BSZ;
#pragma unroll
        for (int ks = 0; ks < 2; ++ks) {
            const int c = t + ks * 8;
            uint32_t bh[TN][2], bl[TN][2];
#pragma unroll
            for (int nt = 0; nt < TN; ++nt) {
                int n = wcol0 + nt * 8 + g;
                bh[nt][0] = Bbh[n * ROWU + c]; bh[nt][1] = Bbh[n * ROWU + c + 4];
                bl[nt][0] = Bbl[n * ROWU + c]; bl[nt][1] = Bbl[n * ROWU + c + 4];
            }
#pragma unroll
            for (int mt = 0; mt < TM; ++mt) {
                int m = wrow0 + mt * 16 + g;
                uint32_t ah[4] = { Abh[m*ROWU+c], Abh[(m+8)*ROWU+c],
                                   Abh[m*ROWU+c+4], Abh[(m+8)*ROWU+c+4] };
                uint32_t al[4] = { Abl[m*ROWU+c], Abl[(m+8)*ROWU+c],
                                   Abl[m*ROWU+c+4], Abl[(m+8)*ROWU+c+4] };
#pragma unroll
                for (int nt = 0; nt < TN; ++nt) {
                    mma16816(acc[mt][nt], ah, bh[nt]);
                    mma16816(acc[mt][nt], ah, bl[nt]);
                    mma16816(acc[mt][nt], al, bh[nt]);
                }
            }
        }
    };

    // prologue
    loadAreg(0);
    cpB(0, 0);
    storeA(0, 0);
    asm volatile("cp.async.wait_group 0;" ::: "memory");
    __syncthreads();

    for (int kt = 0; kt < KT; ++kt) {
        if (kt + 1 < KT) {
            loadAreg(kt + 1);
            cpB(kt + 1, (kt + 1) & 1);
        }
        compute(kt & 1);
        __syncthreads();
        if (kt + 1 < KT) {
            storeA((kt + 1) & 1, kt + 1);
            asm volatile("cp.async.wait_group 0;" ::: "memory");
            __syncthreads();
        }
    }

#pragma unroll
    for (int mt = 0; mt < TM; ++mt) {
#pragma unroll
        for (int nt = 0; nt < TN; ++nt) {
            int m = row0 + wrow0 + mt * 16 + g;
            int n = wcol0 + nt * 8 + 2 * t;
            store_split2(Ch + coff + (long long)m * DM + n,
                         Cl + coff + (long long)m * DM + n,
                         acc[mt][nt][0], acc[mt][nt][1]);
            store_split2(Ch + coff + (long long)(m + 8) * DM + n,
                         Cl + coff + (long long)(m + 8) * DM + n,
                         acc[mt][nt][2], acc[mt][nt][3]);
        }
    }
}

// ---------------------------------------------------------------------------
extern "C" void kernel_launch(void* const* d_in, const int* in_sizes, int n_in,
                              void* d_out, int out_size)
{
    const float* query = (const float*)d_in[0];
    const float* key_  = (const float*)d_in[1];
    const float* value = (const float*)d_in[2];
    const float* W_q   = (const float*)d_in[3];
    const float* b_q   = (const float*)d_in[4];
    const float* W_k   = (const float*)d_in[5];
    const float* b_k   = (const float*)d_in[6];
    const float* W_v   = (const float*)d_in[7];
    const float* b_v   = (const float*)d_in[8];
    const float* W_o   = (const float*)d_in[9];
    const float* b_o   = (const float*)d_in[10];

    float* out = (float*)d_out;

    static bool inited = false;
    static unsigned short *xqh,*xql,*xkh,*xkl,*xvh,*xvl;
    static unsigned short *wqh,*wql,*wkh,*wkl,*wvh,*wvl,*woh,*wol;
    static unsigned short *Qh,*Ql,*Kh,*Kl,*VTh,*VTl,*ch,*cl;
    static float *attn_f, *stats, *rstats;
    if (!inited) {
        inited = true;
        cudaGetSymbolAddress((void**)&xqh, g_xqh); cudaGetSymbolAddress((void**)&xql, g_xql);
        cudaGetSymbolAddress((void**)&xkh, g_xkh); cudaGetSymbolAddress((void**)&xkl, g_xkl);
        cudaGetSymbolAddress((void**)&xvh, g_xvh); cudaGetSymbolAddress((void**)&xvl, g_xvl);
        cudaGetSymbolAddress((void**)&wqh, g_wqh); cudaGetSymbolAddress((void**)&wql, g_wql);
        cudaGetSymbolAddress((void**)&wkh, g_wkh); cudaGetSymbolAddress((void**)&wkl, g_wkl);
        cudaGetSymbolAddress((void**)&wvh, g_wvh); cudaGetSymbolAddress((void**)&wvl, g_wvl);
        cudaGetSymbolAddress((void**)&woh, g_woh); cudaGetSymbolAddress((void**)&wol, g_wol);
        cudaGetSymbolAddress((void**)&Qh,  g_Qh);  cudaGetSymbolAddress((void**)&Ql,  g_Ql);
        cudaGetSymbolAddress((void**)&Kh,  g_Kh);  cudaGetSymbolAddress((void**)&Kl,  g_Kl);
        cudaGetSymbolAddress((void**)&VTh, g_VTh); cudaGetSymbolAddress((void**)&VTl, g_VTl);
        cudaGetSymbolAddress((void**)&ch,  g_ch);  cudaGetSymbolAddress((void**)&cl,  g_cl);
        cudaGetSymbolAddress((void**)&attn_f, g_attn_f);
        cudaGetSymbolAddress((void**)&stats,  g_stats);
        cudaGetSymbolAddress((void**)&rstats, g_rstats);
        cudaFuncSetAttribute(gemm_qkv,   cudaFuncAttributeMaxDynamicSharedMemorySize, 81920);
        cudaFuncSetAttribute(gemm_sp<0>, cudaFuncAttributeMaxDynamicSharedMemorySize, 81920);
        cudaFuncSetAttribute(gemm_sp<3>, cudaFuncAttributeMaxDynamicSharedMemorySize, 81920);
        cudaFuncSetAttribute(gemm_av,    cudaFuncAttributeMaxDynamicSharedMemorySize, 61440);
    }

    const int attn_in_out = ((long long)out_size >= OUT_ELEMS + ATTN_ELEMS) ? 1 : 0;
    float* attn = attn_in_out ? out + OUT_ELEMS : attn_f;

    // 0) split raw inputs (3) + weights (4) to bf16 hi/lo — two batched launches
    {
        int n4i = MROWS * DM / 4;
        int n4w = DM * DM / 4;
        dim3 gi((n4i + 255) / 256, 3);
        split_multi<<<gi, 256>>>((const float4*)query, (const float4*)key_,
                                 (const float4*)value, (const float4*)value,
                                 (uint2*)xqh, (uint2*)xkh, (uint2*)xvh, (uint2*)xvh,
                                 (uint2*)xql, (uint2*)xkl, (uint2*)xvl, (uint2*)xvl,
                                 n4i);
        dim3 gw((n4w + 255) / 256, 4);
        split_multi<<<gw, 256>>>((const float4*)W_q, (const float4*)W_k,
                                 (const float4*)W_v, (const float4*)W_o,
                                 (uint2*)wqh, (uint2*)wkh, (uint2*)wvh, (uint2*)woh,
                                 (uint2*)wql, (uint2*)wkl, (uint2*)wvl, (uint2*)wol,
                                 n4w);
    }

    // 1) merged QKV projections (one launch, grid.z = 3)
    {
        dim3 grd(DM / 128, MROWS / 128, 3);
        gemm_qkv<<<grd, 256, 81920>>>(xqh, xql, xkh, xkl, xvh, xvl,
                                      wqh, wql, wkh, wkl, wvh, wvl,
                                      b_q, b_k, b_v,
                                      Qh, Ql, Kh, Kl, VTh, VTl);
    }

    // 2) scores = (Q.K)/8 -> attn region (raw fp32) + per-tile softmax stats
    {
        dim3 grd(SS / 128, SS / 128, NZ);
        gemm_sp<3><<<grd, 256, 81920>>>(Qh, Ql, Kh, Kl, nullptr,
                                        attn, stats,
                                        DH, DM, DM, SS, 0.125f, NH,
                                        (long long)SS * DM, DH,
                                        (long long)SS * DM, DH,
                                        (long long)NH * SS * SS, (long long)SS * SS);
    }

    // 3) reduce per-tile stats -> per-row (max, 1/sum)
    rowstats_reduce<<<NZ * SS / 8, 256>>>(stats, rstats);

    // 4) ctx = softmax(scores) @ V, softmax applied in-register; writes
    //    normalized probs to attn output iff attn is part of d_out.
    {
        dim3 grd(1, SS / 128, NZ);
        gemm_av<<<grd, 256, 61440>>>(attn, attn, rstats, VTh, VTl, ch, cl, attn_in_out);
    }

    // 5) out = ctx @ W_o^T + b_o (fp32)
    {
        dim3 grd(DM / 128, MROWS / 128, 1);
        gemm_sp<0><<<grd, 256, 81920>>>(ch, cl, woh, wol, b_o,
                                        out, nullptr,
                                        DM, DM, DM, DM, 1.0f, 1,
                                        0,0,0,0,0,0);
    }
}